// round 9
// baseline (speedup 1.0000x reference)
#include <cuda_runtime.h>
#include <math.h>
#include <limits.h>

// Problem constants
#define NTOK 50176            // 16 * 56 * 56
#define CDIM 96
#define QKVDIM 288
#define HIDDIM 384
#define LITDIM 768
#define NCLAUSE 128
#define NWIN 1024             // 16 * 8 * 8
#define IMGHW 56
#define LNEPS 1e-5f

// ---------------- scratch (static device arrays; no allocation) -------------
__device__ float g_mu [(size_t)NTOK];
__device__ float g_rs [(size_t)NTOK];
__device__ float g_qkv[(size_t)NTOK * QKVDIM];
__device__ float g_ao [(size_t)NTOK * CDIM];
__device__ float g_x1 [(size_t)NTOK * CDIM];
__device__ float g_w  [(size_t)NTOK * CDIM];
__device__ float g_ll [(size_t)NTOK * LITDIM];
__device__ float g_cl [(size_t)NTOK * NCLAUSE];
__device__ int   g_skip;     // 1 => TM-FFN branch provably ~0, take fast path

// ---------------- helpers ---------------------------------------------------
__device__ __forceinline__ float warp_sum(float v) {
#pragma unroll
    for (int o = 16; o > 0; o >>= 1) v += __shfl_xor_sync(0xffffffffu, v, o);
    return v;
}

// packed f32x2 helpers (FFMA2 is PTX-only; ptxas never auto-fuses)
__device__ __forceinline__ unsigned long long pack2(float lo, float hi) {
    unsigned long long r;
    asm("mov.b64 %0, {%1, %2};" : "=l"(r) : "f"(lo), "f"(hi));
    return r;
}
__device__ __forceinline__ void unpack2(unsigned long long v, float& lo, float& hi) {
    asm("mov.b64 {%0, %1}, %2;" : "=f"(lo), "=f"(hi) : "l"(v));
}
__device__ __forceinline__ unsigned long long fma2(
    unsigned long long a, unsigned long long b, unsigned long long c) {
    unsigned long long d;
    asm("fma.rn.f32x2 %0, %1, %2, %3;" : "=l"(d) : "l"(a), "l"(b), "l"(c));
    return d;
}

// ---------------- guard: is the clause branch provably negligible? ----------
// For every clause c, any literal pair (j, j+384) with BOTH mask bits set
// contributes log(max(y,eps)) + log(max(1-y,eps)) <= log(1/4) to the clause
// exponent S. Hence S <= -1.386 * n_both(c) and
//   |logits| <= NCLAUSE * max|tm_out| * exp(-1.386 * min_c n_both(c)).
// If that bound < 1e-25, replacing logits by 0 perturbs the output by < 1e-25:
// take the fast path. Otherwise run the full path.
__global__ void guard_kernel(const float* __restrict__ tm_inc,
                             const float* __restrict__ tm_out,
                             int* __restrict__ flag)
{
    __shared__ int   cnt[256];
    __shared__ float mxs[256];
    int t = threadIdx.x;
    int c = t >> 1, half = t & 1;
    int cn = 0;
    for (int j = half * 192; j < half * 192 + 192; j++) {
        float a = tm_inc[(size_t)c * LITDIM + j];
        float b = tm_inc[(size_t)c * LITDIM + HIDDIM + j];
        cn += (a > 0.0f && b > 0.0f) ? 1 : 0;
    }
    cnt[t] = cn;
    float m = 0.0f;
    for (int i = t; i < NCLAUSE * CDIM; i += 256)
        m = fmaxf(m, fabsf(tm_out[i]));
    mxs[t] = m;
    __syncthreads();
    if (t == 0) {
        int mn = INT_MAX;
        for (int i = 0; i < NCLAUSE; i++) {
            int v = cnt[2 * i] + cnt[2 * i + 1];
            mn = (v < mn) ? v : mn;
        }
        float M = 0.0f;
        for (int i = 0; i < 256; i++) M = fmaxf(M, mxs[i]);
        float logbound = logf((float)NCLAUSE * M + 1e-30f) - 1.3862944f * (float)mn;
        flag[0] = (logbound < -57.6f) ? 1 : 0;   // e^-57.6 ~ 1e-25
    }
}

// ---------------- LN1 stats only (mean + rstd per token) ---------------------
__global__ __launch_bounds__(256) void ln1_stats(
    const float* __restrict__ x, float* __restrict__ mu, float* __restrict__ rs)
{
    int warp = (blockIdx.x * blockDim.x + threadIdx.x) >> 5;
    int lane = threadIdx.x & 31;
    if (warp >= NTOK) return;
    size_t base = (size_t)warp * CDIM;
    float v0 = x[base + lane];
    float v1 = x[base + lane + 32];
    float v2 = x[base + lane + 64];
    float mean = warp_sum(v0 + v1 + v2) * (1.0f / CDIM);
    float d0 = v0 - mean, d1 = v1 - mean, d2 = v2 - mean;
    float var = warp_sum(d0 * d0 + d1 * d1 + d2 * d2) * (1.0f / CDIM);
    if (lane == 0) {
        mu[warp] = mean;
        rs[warp] = rsqrtf(var + LNEPS);
    }
}

// double layernorm: w = LN(LN(x1, g2, b2), fg, fb); early-exit on fast path
__global__ __launch_bounds__(256) void ln2_kernel(
    const float* __restrict__ x, const float* __restrict__ g2,
    const float* __restrict__ b2, const float* __restrict__ fg,
    const float* __restrict__ fb, float* __restrict__ y,
    const int* __restrict__ flag)
{
    if (flag[0]) return;
    int warp = (blockIdx.x * blockDim.x + threadIdx.x) >> 5;
    int lane = threadIdx.x & 31;
    if (warp >= NTOK) return;
    size_t base = (size_t)warp * CDIM;
    float v0 = x[base + lane];
    float v1 = x[base + lane + 32];
    float v2 = x[base + lane + 64];
    float mean = warp_sum(v0 + v1 + v2) * (1.0f / CDIM);
    float d0 = v0 - mean, d1 = v1 - mean, d2 = v2 - mean;
    float var = warp_sum(d0 * d0 + d1 * d1 + d2 * d2) * (1.0f / CDIM);
    float rsv = rsqrtf(var + LNEPS);
    float z0 = d0 * rsv * g2[lane]      + b2[lane];
    float z1 = d1 * rsv * g2[lane + 32] + b2[lane + 32];
    float z2 = d2 * rsv * g2[lane + 64] + b2[lane + 64];
    float m2 = warp_sum(z0 + z1 + z2) * (1.0f / CDIM);
    float e0 = z0 - m2, e1 = z1 - m2, e2 = z2 - m2;
    float var2 = warp_sum(e0 * e0 + e1 * e1 + e2 * e2) * (1.0f / CDIM);
    float rs2 = rsqrtf(var2 + LNEPS);
    y[base + lane]      = e0 * rs2 * fg[lane]      + fb[lane];
    y[base + lane + 32] = e1 * rs2 * fg[lane + 32] + fb[lane + 32];
    y[base + lane + 64] = e2 * rs2 * fg[lane + 64] + fb[lane + 64];
}

// ---------------- fp32 GEMM, BN=96 exact, f32x2 packed inner loop ------------
// C[M x N] = A[M x K] @ B^T (+bias), B is N x K. N multiple of 96, K % 16 == 0.
// LNA: apply per-token layernorm to A during load:
//      a = (x - mu[m]) * rs[m] * gamma[k] + beta[k]
// MODE 1: C = acc + bias[n]
// MODE 2: C = ex1[m*96+n] + acc + bias[n]
template<int MODE, bool LNA>
__global__ __launch_bounds__(256, 2) void gemm96_k(
    const float* __restrict__ A, const float* __restrict__ B,
    const float* __restrict__ bias, const float* __restrict__ ex1,
    float* __restrict__ C, int M, int N, int K, int ldc,
    const float* __restrict__ MU, const float* __restrict__ RS,
    const float* __restrict__ LNG, const float* __restrict__ LNB)
{
    const int BM = 128, BN = 96, BK = 16;
    __shared__ __align__(16) float As[2][BK][BM + 4];
    __shared__ __align__(16) float Bs[2][BK][BN + 4];
    __shared__ float gsm[CDIM], bsm[CDIM];

    int tid = threadIdx.x;
    int m0 = blockIdx.x * BM;
    int n0 = blockIdx.y * BN;
    int tx = tid & 15;        // 16 col groups of 6
    int ty = tid >> 4;        // 16 row groups

    int lr = tid >> 1;        // A row (0..127)
    int lk = (tid & 1) * 8;   // A k offset
    int br = tid >> 1;        // B row (0..95) for tid<192
    int bk2 = (tid & 1) * 8;

    if (LNA) {
        if (tid < CDIM) { gsm[tid] = LNG[tid]; bsm[tid] = LNB[tid]; }
        __syncthreads();
    }

    unsigned long long acc2[4][6];
#pragma unroll
    for (int i = 0; i < 4; i++)
#pragma unroll
        for (int j = 0; j < 6; j++) acc2[i][j] = 0ull;

    float ldA[8], ldB[8];
    int KT = K / BK;

#define G96_LOAD(kt)                                                         \
    {                                                                        \
        const float* ap = A + (size_t)(m0 + lr) * K + (kt) * BK + lk;        \
        *(float4*)&ldA[0] = *(const float4*)ap;                              \
        *(float4*)&ldA[4] = *(const float4*)(ap + 4);                        \
        if (LNA) {                                                           \
            float muv = MU[m0 + lr], rsv = RS[m0 + lr];                      \
            _Pragma("unroll")                                                \
            for (int j = 0; j < 8; j++) {                                    \
                int kk = (kt) * BK + lk + j;                                 \
                ldA[j] = (ldA[j] - muv) * rsv * gsm[kk] + bsm[kk];           \
            }                                                                \
        }                                                                    \
        if (tid < 192) {                                                     \
            const float* bp = B + (size_t)(n0 + br) * K + (kt) * BK + bk2;   \
            *(float4*)&ldB[0] = *(const float4*)bp;                          \
            *(float4*)&ldB[4] = *(const float4*)(bp + 4);                    \
        }                                                                    \
    }

#define G96_STS(bsel)                                                        \
    {                                                                        \
        _Pragma("unroll")                                                    \
        for (int j = 0; j < 8; j++) As[bsel][lk + j][lr] = ldA[j];           \
        if (tid < 192) {                                                     \
            _Pragma("unroll")                                                \
            for (int j = 0; j < 8; j++) Bs[bsel][bk2 + j][br] = ldB[j];      \
        }                                                                    \
    }

    G96_LOAD(0);
    G96_STS(0);
    __syncthreads();

    int buf = 0;
    for (int kt = 0; kt < KT; kt++) {
        if (kt + 1 < KT) G96_LOAD(kt + 1);
#pragma unroll
        for (int k = 0; k < BK; k++) {
            // a pairs: rows (ty*4,+1),(+2,+3),(+64,+65),(+66,+67)
            ulonglong2 pa = *(const ulonglong2*)&As[buf][k][ty * 4];
            ulonglong2 pb = *(const ulonglong2*)&As[buf][k][ty * 4 + 64];
            unsigned long long ap[4] = {pa.x, pa.y, pb.x, pb.y};
#pragma unroll
            for (int j = 0; j < 6; j++) {
                float bj = Bs[buf][k][tx * 6 + j];
                unsigned long long b2 = pack2(bj, bj);
#pragma unroll
                for (int ip = 0; ip < 4; ip++)
                    acc2[ip][j] = fma2(ap[ip], b2, acc2[ip][j]);
            }
        }
        if (kt + 1 < KT) {
            G96_STS(buf ^ 1);
            __syncthreads();
        }
        buf ^= 1;
    }

#pragma unroll
    for (int ip = 0; ip < 4; ip++) {
        int mb = m0 + ty * 4 + (ip & 1) * 2 + (ip >> 1) * 64;
#pragma unroll
        for (int j = 0; j < 6; j++) {
            int n = n0 + tx * 6 + j;
            float lo, hi;
            unpack2(acc2[ip][j], lo, hi);
            if (MODE == 1) {
                C[(size_t)mb * ldc + n]       = lo + bias[n];
                C[(size_t)(mb + 1) * ldc + n] = hi + bias[n];
            } else {
                C[(size_t)mb * ldc + n]       = ex1[(size_t)mb * CDIM + n] + lo + bias[n];
                C[(size_t)(mb + 1) * ldc + n] = ex1[(size_t)(mb + 1) * CDIM + n] + hi + bias[n];
            }
        }
    }
#undef G96_LOAD
#undef G96_STS
}

// ---------------- fp32 tiled GEMM, 128x128x16 (modes 3,4,5; full path only) --
// SKIP: 1 = early-exit whole kernel when flag set; 2 = fast-path final write.
template<int MODE, bool BTRANS, bool BMASK, int SKIP>
__global__ __launch_bounds__(256, 2) void gemm2_k(
    const float* __restrict__ A, const float* __restrict__ B,
    const float* __restrict__ bias, const float* __restrict__ ex1,
    const float* __restrict__ ex2, float* __restrict__ C,
    int M, int N, int K, int ldc, const int* __restrict__ flag)
{
    const int BM = 128, BN = 128, BK = 16;

    int tid = threadIdx.x;
    int m0 = blockIdx.x * BM;
    int n0 = blockIdx.y * BN;
    int tx = tid & 15;
    int ty = tid >> 4;

    if (SKIP == 1) {
        if (flag[0]) return;
    }
    if (SKIP == 2) {
        if (flag[0]) {
            float gte = 1.0f / (1.0f + expf(-ex2[0]));
            float add = (1.0f - gte) * 0.5f;
#pragma unroll
            for (int i = 0; i < 8; i++) {
                int m = m0 + ty * 4 + (i < 4 ? i : 60 + i);
#pragma unroll
                for (int j = 0; j < 8; j++) {
                    int n = n0 + tx * 4 + (j < 4 ? j : 60 + j);
                    if (n >= N) continue;
                    C[(size_t)m * ldc + n] = ex1[(size_t)m * CDIM + n] + add;
                }
            }
            return;
        }
    }

    __shared__ __align__(16) float As[2][BK][BM + 4];
    __shared__ __align__(16) float Bs[2][BK][BN + 4];

    int lr = tid >> 1;
    int lk = (tid & 1) * 8;
    int bk = tid >> 4;
    int bn = (tid & 15) * 8;

    float acc[8][8];
#pragma unroll
    for (int i = 0; i < 8; i++)
#pragma unroll
        for (int j = 0; j < 8; j++) acc[i][j] = 0.0f;

    float ldA[8], ldB[8];
    int KT = K / BK;

#define GEMM_LOAD(kt)                                                        \
    {                                                                        \
        const float* ap = A + (size_t)(m0 + lr) * K + (kt) * BK + lk;        \
        *(float4*)&ldA[0] = *(const float4*)ap;                              \
        *(float4*)&ldA[4] = *(const float4*)(ap + 4);                        \
        if (!BTRANS) {                                                       \
            int n = n0 + lr;                                                 \
            if (n < N) {                                                     \
                const float* bp = B + (size_t)n * K + (kt) * BK + lk;        \
                *(float4*)&ldB[0] = *(const float4*)bp;                      \
                *(float4*)&ldB[4] = *(const float4*)(bp + 4);                \
            } else {                                                         \
                _Pragma("unroll")                                            \
                for (int j = 0; j < 8; j++) ldB[j] = 0.0f;                   \
            }                                                                \
            if (BMASK) {                                                     \
                _Pragma("unroll")                                            \
                for (int j = 0; j < 8; j++)                                  \
                    ldB[j] = (ldB[j] > 0.0f) ? 1.0f : 0.0f;                  \
            }                                                                \
        } else {                                                             \
            _Pragma("unroll")                                                \
            for (int j = 0; j < 8; j++) {                                    \
                int n = n0 + bn + j;                                         \
                ldB[j] = (n < N)                                             \
                    ? B[(size_t)((kt) * BK + bk) * N + n] : 0.0f;            \
            }                                                                \
        }                                                                    \
    }

#define GEMM_STS(bsel)                                                       \
    {                                                                        \
        _Pragma("unroll")                                                    \
        for (int j = 0; j < 8; j++) As[bsel][lk + j][lr] = ldA[j];           \
        if (!BTRANS) {                                                       \
            _Pragma("unroll")                                                \
            for (int j = 0; j < 8; j++) Bs[bsel][lk + j][lr] = ldB[j];       \
        } else {                                                             \
            _Pragma("unroll")                                                \
            for (int j = 0; j < 8; j++) Bs[bsel][bk][bn + j] = ldB[j];       \
        }                                                                    \
    }

    GEMM_LOAD(0);
    GEMM_STS(0);
    __syncthreads();

    int buf = 0;
    for (int kt = 0; kt < KT; kt++) {
        if (kt + 1 < KT) GEMM_LOAD(kt + 1);
#pragma unroll
        for (int k = 0; k < BK; k++) {
            float4 a0 = *(const float4*)&As[buf][k][ty * 4];
            float4 a1 = *(const float4*)&As[buf][k][ty * 4 + 64];
            float4 b0 = *(const float4*)&Bs[buf][k][tx * 4];
            float4 b1 = *(const float4*)&Bs[buf][k][tx * 4 + 64];
            float a[8] = {a0.x, a0.y, a0.z, a0.w, a1.x, a1.y, a1.z, a1.w};
            float b[8] = {b0.x, b0.y, b0.z, b0.w, b1.x, b1.y, b1.z, b1.w};
#pragma unroll
            for (int i = 0; i < 8; i++)
#pragma unroll
                for (int j = 0; j < 8; j++) acc[i][j] += a[i] * b[j];
        }
        if (kt + 1 < KT) {
            GEMM_STS(buf ^ 1);
            __syncthreads();
        }
        buf ^= 1;
    }

    float gte = 0.0f;
    if (MODE == 5) gte = 1.0f / (1.0f + expf(-ex2[0]));
#pragma unroll
    for (int i = 0; i < 8; i++) {
        int m = m0 + ty * 4 + (i < 4 ? i : 60 + i);
#pragma unroll
        for (int j = 0; j < 8; j++) {
            int n = n0 + tx * 4 + (j < 4 ? j : 60 + j);
            if (n >= N) continue;
            float v = acc[i][j];
            if (MODE == 3) {
                float y = 1.0f / (1.0f + expf(-(v + bias[n])));
                C[(size_t)m * LITDIM + n]          = logf(fmaxf(y, 1e-6f));
                C[(size_t)m * LITDIM + HIDDIM + n] = logf(fmaxf(1.0f - y, 1e-6f));
            } else if (MODE == 4) {
                C[(size_t)m * ldc + n] = expf(v);
            } else if (MODE == 5) {
                float s = 1.0f / (1.0f + expf(-v));
                C[(size_t)m * ldc + n] = ex1[(size_t)m * CDIM + n] + gte * v + (1.0f - gte) * s;
            }
        }
    }
#undef GEMM_LOAD
#undef GEMM_STS
}

// ---------------- windowed attention, one block per (window, head) -----------
// grid (NWIN, 3), block 128. 4x4 score micro-tiles, f32x2 packed along d.
__global__ __launch_bounds__(128) void attn2_kernel(
    const float* __restrict__ qkv, float* __restrict__ ao)
{
    __shared__ __align__(16) float qs[52][44];   // rows 49..51: pad (garbage ok)
    __shared__ __align__(16) float ks[52][44];
    __shared__ __align__(16) float vs[49][44];
    __shared__ float ps[52][53];
    __shared__ int ltab[49];
    __shared__ int otab[49];

    int w  = blockIdx.x;
    int h  = blockIdx.y;
    int b  = w >> 6;
    int wh = (w >> 3) & 7;
    int ww = w & 7;
    int tid = threadIdx.x;

    if (tid < 49) {
        int th = tid / 7, tw = tid % 7;
        int r = (wh * 7 + th + 3) % IMGHW;
        int c = (ww * 7 + tw + 3) % IMGHW;
        ltab[tid] = b * (IMGHW * IMGHW) + r * IMGHW + c;
        int ro = wh * 7 + (th + 3) % 7;          // intra-window inverse roll
        int co = ww * 7 + (tw + 3) % 7;
        otab[tid] = b * (IMGHW * IMGHW) + ro * IMGHW + co;
    }
    __syncthreads();

    // load q/k/v for this head: 49 tokens x 8 d-quads
    for (int i = tid; i < 49 * 8; i += 128) {
        int t = i >> 3, dq = (i & 7) * 4;
        const float* base = qkv + (size_t)ltab[t] * QKVDIM + h * 32 + dq;
        *(float4*)&qs[t][dq] = *(const float4*)base;
        *(float4*)&ks[t][dq] = *(const float4*)(base + 96);
        *(float4*)&vs[t][dq] = *(const float4*)(base + 192);
    }
    __syncthreads();

    const float scale = 0.17677669529663687f;  // 1/sqrt(32)

    // scores: 13x13 grid of 4x4 tiles, accumulators packed over d-pairs
    for (int tile = tid; tile < 169; tile += 128) {
        int rp = tile % 13, cp = tile / 13;
        int r0 = rp * 4, c0 = cp * 4;
        unsigned long long acc2[4][4];
#pragma unroll
        for (int i = 0; i < 4; i++)
#pragma unroll
            for (int j = 0; j < 4; j++) acc2[i][j] = 0ull;
#pragma unroll
        for (int dq = 0; dq < 32; dq += 4) {
            ulonglong2 q2[4], k2[4];
#pragma unroll
            for (int i = 0; i < 4; i++)
                q2[i] = *(const ulonglong2*)&qs[r0 + i][dq];
#pragma unroll
            for (int j = 0; j < 4; j++)
                k2[j] = *(const ulonglong2*)&ks[c0 + j][dq];
#pragma unroll
            for (int i = 0; i < 4; i++)
#pragma unroll
                for (int j = 0; j < 4; j++) {
                    acc2[i][j] = fma2(q2[i].x, k2[j].x, acc2[i][j]);
                    acc2[i][j] = fma2(q2[i].y, k2[j].y, acc2[i][j]);
                }
        }
#pragma unroll
        for (int i = 0; i < 4; i++) {
            if (r0 + i >= 49) continue;
#pragma unroll
            for (int j = 0; j < 4; j++) {
                if (c0 + j >= 49) continue;
                float lo, hi;
                unpack2(acc2[i][j], lo, hi);
                ps[r0 + i][c0 + j] = (lo + hi) * scale;
            }
        }
    }
    __syncthreads();

    // softmax per row
    if (tid < 49) {
        float mx = -1e30f;
        for (int j = 0; j < 49; j++) mx = fmaxf(mx, ps[tid][j]);
        float sum = 0.0f;
        for (int j = 0; j < 49; j++) {
            float e = expf(ps[tid][j] - mx);
            ps[tid][j] = e;
            sum += e;
        }
        float inv = 1.0f / sum;
        for (int j = 0; j < 49; j++) ps[tid][j] *= inv;
    }
    __syncthreads();

    // AV: 13 token-groups x 8 d-quads = 104 tiles; 4 tokens x 4 dims, packed
    for (int tile = tid; tile < 104; tile += 128) {
        int tg = tile >> 3, dq = (tile & 7) * 4;
        int t0 = tg * 4;
        unsigned long long acc2[4][2];
#pragma unroll
        for (int it = 0; it < 4; it++) { acc2[it][0] = 0ull; acc2[it][1] = 0ull; }
        for (int j = 0; j < 49; j++) {
            ulonglong2 v2 = *(const ulonglong2*)&vs[j][dq];
#pragma unroll
            for (int it = 0; it < 4; it++) {
                float p = ps[t0 + it][j];   // rows 49..51 garbage, never stored
                unsigned long long p2 = pack2(p, p);
                acc2[it][0] = fma2(p2, v2.x, acc2[it][0]);
                acc2[it][1] = fma2(p2, v2.y, acc2[it][1]);
            }
        }
#pragma unroll
        for (int it = 0; it < 4; it++) {
            int t = t0 + it;
            if (t < 49) {
                float4 o;
                unpack2(acc2[it][0], o.x, o.y);
                unpack2(acc2[it][1], o.z, o.w);
                *(float4*)&ao[(size_t)otab[t] * CDIM + h * 32 + dq] = o;
            }
        }
    }
}

// ---------------- host launcher ----------------------------------------------
extern "C" void kernel_launch(void* const* d_in, const int* in_sizes, int n_in,
                              void* d_out, int out_size)
{
    const float* x       = (const float*)d_in[0];
    const float* n1g     = (const float*)d_in[1];
    const float* n1b     = (const float*)d_in[2];
    const float* qkv_w   = (const float*)d_in[3];
    const float* qkv_b   = (const float*)d_in[4];
    const float* proj_w  = (const float*)d_in[5];
    const float* proj_b  = (const float*)d_in[6];
    const float* n2g     = (const float*)d_in[7];
    const float* n2b     = (const float*)d_in[8];
    const float* fng     = (const float*)d_in[9];
    const float* fnb     = (const float*)d_in[10];
    const float* pin_w   = (const float*)d_in[11];
    const float* pin_b   = (const float*)d_in[12];
    const float* tm_inc  = (const float*)d_in[13];
    const float* tm_out  = (const float*)d_in[14];
    const float* gate    = (const float*)d_in[15];
    float* out           = (float*)d_out;

    float *p_mu, *p_rs, *p_qkv, *p_ao, *p_x1, *p_w, *p_ll, *p_cl;
    int* p_skip;
    cudaGetSymbolAddress((void**)&p_mu,  g_mu);
    cudaGetSymbolAddress((void**)&p_rs,  g_rs);
    cudaGetSymbolAddress((void**)&p_qkv, g_qkv);
    cudaGetSymbolAddress((void**)&p_ao,  g_ao);
    cudaGetSymbolAddress((void**)&p_x1,  g_x1);
    cudaGetSymbolAddress((void**)&p_w,   g_w);
    cudaGetSymbolAddress((void**)&p_ll,  g_ll);
    cudaGetSymbolAddress((void**)&p_cl,  g_cl);
    cudaGetSymbolAddress((void**)&p_skip, g_skip);

    const int MB = NTOK / 128;  // 392

    // 0) guard: decide whether the clause branch is provably negligible
    guard_kernel<<<1, 256>>>(tm_inc, tm_out, p_skip);

    // 1) LN1 stats (mean/rstd only; LN applied inside the qkv GEMM A-load)
    ln1_stats<<<NTOK / 8, 256>>>(x, p_mu, p_rs);

    // 2) QKV GEMM with fused LN1: (50176 x 96) @ (288 x 96)^T + b
    gemm96_k<1, true><<<dim3(MB, QKVDIM / 96), 256>>>(
        x, qkv_w, qkv_b, nullptr, p_qkv, NTOK, QKVDIM, CDIM, QKVDIM,
        p_mu, p_rs, n1g, n1b);

    // 3) windowed attention: one block per (window, head)
    attn2_kernel<<<dim3(NWIN, 3), 128>>>(p_qkv, p_ao);

    // 4) proj + residual: x1 = x + ao @ proj_w^T + b
    gemm96_k<2, false><<<dim3(MB, 1), 256>>>(
        p_ao, proj_w, proj_b, x, p_x1, NTOK, CDIM, CDIM, CDIM,
        nullptr, nullptr, nullptr, nullptr);

    // 5) double layernorm -> g_w   (skipped on fast path)
    ln2_kernel<<<NTOK / 8, 256>>>(p_x1, n2g, n2b, fng, fnb, p_w, p_skip);

    // 6) pin GEMM + sigmoid + log-literals -> g_ll   (skipped on fast path)
    gemm2_k<3, false, false, 1><<<dim3(MB, (HIDDIM + 127) / 128), 256>>>(
        p_w, pin_w, pin_b, nullptr, nullptr, p_ll,
        NTOK, HIDDIM, CDIM, LITDIM, p_skip);

    // 7) clause GEMM, binary mask, exp epilogue -> g_cl (skipped on fast path)
    gemm2_k<4, false, true, 1><<<dim3(MB, 1), 256>>>(
        p_ll, tm_inc, nullptr, nullptr, nullptr, p_cl,
        NTOK, NCLAUSE, LITDIM, NCLAUSE, p_skip);

    // 8) final: full GEMM normally; on fast path writes x1 + (1-g)*0.5
    gemm2_k<5, true, false, 2><<<dim3(MB, 1), 256>>>(
        p_cl, tm_out, nullptr, p_x1, gate, out,
        NTOK, CDIM, NCLAUSE, CDIM, p_skip);

    (void)in_sizes; (void)n_in; (void)out_size;
}

// round 10
// speedup vs baseline: 1.2437x; 1.2437x over previous
#include <cuda_runtime.h>
#include <math.h>
#include <limits.h>

// Problem constants
#define NTOK 50176            // 16 * 56 * 56
#define CDIM 96
#define QKVDIM 288
#define HIDDIM 384
#define LITDIM 768
#define NCLAUSE 128
#define NWIN 1024             // 16 * 8 * 8
#define IMGHW 56
#define LNEPS 1e-5f

// ---------------- scratch (static device arrays; no allocation) -------------
__device__ float g_mu [(size_t)NTOK];
__device__ float g_rs [(size_t)NTOK];
__device__ float g_qkv[(size_t)NTOK * QKVDIM];
__device__ float g_ao [(size_t)NTOK * CDIM];
__device__ float g_x1 [(size_t)NTOK * CDIM];
__device__ float g_w  [(size_t)NTOK * CDIM];
__device__ float g_ll [(size_t)NTOK * LITDIM];
__device__ float g_cl [(size_t)NTOK * NCLAUSE];
__device__ int   g_skip;     // 1 => TM-FFN branch provably ~0, take fast path

// ---------------- helpers ---------------------------------------------------
__device__ __forceinline__ float warp_sum(float v) {
#pragma unroll
    for (int o = 16; o > 0; o >>= 1) v += __shfl_xor_sync(0xffffffffu, v, o);
    return v;
}

// ---------------- guard: is the clause branch provably negligible? ----------
// For every clause c, any literal pair (j, j+384) with BOTH mask bits set
// contributes log(max(y,eps)) + log(max(1-y,eps)) <= log(1/4) to the clause
// exponent S. Hence S <= -1.386 * n_both(c) and
//   |logits| <= NCLAUSE * max|tm_out| * exp(-1.386 * min_c n_both(c)).
// If that bound < 1e-25, replacing logits by 0 perturbs the output by < 1e-25:
// take the fast path. Otherwise run the full, exact path.
// 1024 threads + float4 so the single block isn't DRAM-latency-bound.
__global__ __launch_bounds__(1024) void guard_kernel(
    const float* __restrict__ tm_inc, const float* __restrict__ tm_out,
    int* __restrict__ flag)
{
    __shared__ int   cnt[1024];
    __shared__ int   csum[NCLAUSE];
    __shared__ float mxs[1024];
    int t = threadIdx.x;
    int c = t >> 3, sub = t & 7;      // 8 threads per clause, 48 pairs each
    const float4* rowA = (const float4*)(tm_inc + (size_t)c * LITDIM);
    const float4* rowB = (const float4*)(tm_inc + (size_t)c * LITDIM + HIDDIM);
    int cn = 0;
    int base = sub * 12;              // 12 float4 = 48 floats
#pragma unroll
    for (int q = 0; q < 12; q++) {
        float4 a = rowA[base + q];
        float4 b = rowB[base + q];
        cn += (a.x > 0.0f && b.x > 0.0f) ? 1 : 0;
        cn += (a.y > 0.0f && b.y > 0.0f) ? 1 : 0;
        cn += (a.z > 0.0f && b.z > 0.0f) ? 1 : 0;
        cn += (a.w > 0.0f && b.w > 0.0f) ? 1 : 0;
    }
    cnt[t] = cn;
    float m = 0.0f;
    const float4* to4 = (const float4*)tm_out;   // 12288 floats = 3072 float4
#pragma unroll
    for (int q = 0; q < 3; q++) {
        float4 v = to4[t + q * 1024];
        m = fmaxf(m, fmaxf(fmaxf(fabsf(v.x), fabsf(v.y)),
                           fmaxf(fabsf(v.z), fabsf(v.w))));
    }
    mxs[t] = m;
    __syncthreads();
    if (t < NCLAUSE) {
        int s = 0;
#pragma unroll
        for (int i = 0; i < 8; i++) s += cnt[t * 8 + i];
        csum[t] = s;
    }
    __syncthreads();
    if (t == 0) {
        int mn = INT_MAX;
        for (int i = 0; i < NCLAUSE; i++) mn = (csum[i] < mn) ? csum[i] : mn;
        float M = 0.0f;
        for (int i = 0; i < 1024; i++) M = fmaxf(M, mxs[i]);
        float logbound = logf((float)NCLAUSE * M + 1e-30f) - 1.3862944f * (float)mn;
        flag[0] = (logbound < -57.6f) ? 1 : 0;   // e^-57.6 ~ 1e-25
    }
}

// ---------------- LN1 stats only (mean + rstd per token) ---------------------
__global__ __launch_bounds__(256) void ln1_stats(
    const float* __restrict__ x, float* __restrict__ mu, float* __restrict__ rs)
{
    int warp = (blockIdx.x * blockDim.x + threadIdx.x) >> 5;
    int lane = threadIdx.x & 31;
    if (warp >= NTOK) return;
    size_t base = (size_t)warp * CDIM;
    float v0 = x[base + lane];
    float v1 = x[base + lane + 32];
    float v2 = x[base + lane + 64];
    float mean = warp_sum(v0 + v1 + v2) * (1.0f / CDIM);
    float d0 = v0 - mean, d1 = v1 - mean, d2 = v2 - mean;
    float var = warp_sum(d0 * d0 + d1 * d1 + d2 * d2) * (1.0f / CDIM);
    if (lane == 0) {
        mu[warp] = mean;
        rs[warp] = rsqrtf(var + LNEPS);
    }
}

// double layernorm: w = LN(LN(x1, g2, b2), fg, fb); early-exit on fast path
__global__ __launch_bounds__(256) void ln2_kernel(
    const float* __restrict__ x, const float* __restrict__ g2,
    const float* __restrict__ b2, const float* __restrict__ fg,
    const float* __restrict__ fb, float* __restrict__ y,
    const int* __restrict__ flag)
{
    if (flag[0]) return;
    int warp = (blockIdx.x * blockDim.x + threadIdx.x) >> 5;
    int lane = threadIdx.x & 31;
    if (warp >= NTOK) return;
    size_t base = (size_t)warp * CDIM;
    float v0 = x[base + lane];
    float v1 = x[base + lane + 32];
    float v2 = x[base + lane + 64];
    float mean = warp_sum(v0 + v1 + v2) * (1.0f / CDIM);
    float d0 = v0 - mean, d1 = v1 - mean, d2 = v2 - mean;
    float var = warp_sum(d0 * d0 + d1 * d1 + d2 * d2) * (1.0f / CDIM);
    float rsv = rsqrtf(var + LNEPS);
    float z0 = d0 * rsv * g2[lane]      + b2[lane];
    float z1 = d1 * rsv * g2[lane + 32] + b2[lane + 32];
    float z2 = d2 * rsv * g2[lane + 64] + b2[lane + 64];
    float m2 = warp_sum(z0 + z1 + z2) * (1.0f / CDIM);
    float e0 = z0 - m2, e1 = z1 - m2, e2 = z2 - m2;
    float var2 = warp_sum(e0 * e0 + e1 * e1 + e2 * e2) * (1.0f / CDIM);
    float rs2 = rsqrtf(var2 + LNEPS);
    y[base + lane]      = e0 * rs2 * fg[lane]      + fb[lane];
    y[base + lane + 32] = e1 * rs2 * fg[lane + 32] + fb[lane + 32];
    y[base + lane + 64] = e2 * rs2 * fg[lane + 64] + fb[lane + 64];
}

// ---------------- fp32 GEMM, BN=96 exact, scalar 8x6 micro (round-8 form) ----
// C[M x N] = A[M x K] @ B^T (+bias), B is N x K. N multiple of 96, K % 16 == 0.
// LNA: apply per-token layernorm to A during load.
// MODE 1: C = acc + bias[n]
// MODE 2 (proj): full path -> C    = ex1 + acc + bias
//                fast path -> Cfast = ex1 + acc + bias + (1-sigmoid(gate))*0.5
template<int MODE, bool LNA>
__global__ __launch_bounds__(256, 2) void gemm96_k(
    const float* __restrict__ A, const float* __restrict__ B,
    const float* __restrict__ bias, const float* __restrict__ ex1,
    float* __restrict__ C, int M, int N, int K, int ldc,
    const float* __restrict__ MU, const float* __restrict__ RS,
    const float* __restrict__ LNG, const float* __restrict__ LNB,
    float* __restrict__ Cfast, const float* __restrict__ gatep,
    const int* __restrict__ flag)
{
    const int BM = 128, BN = 96, BK = 16;
    __shared__ __align__(16) float As[2][BK][BM + 4];
    __shared__ __align__(16) float Bs[2][BK][BN + 4];
    __shared__ float gsm[CDIM], bsm[CDIM];

    int tid = threadIdx.x;
    int m0 = blockIdx.x * BM;
    int n0 = blockIdx.y * BN;
    int tx = tid & 15;        // 16 col groups of 6
    int ty = tid >> 4;        // 16 row groups

    int lr = tid >> 1;        // A row (0..127)
    int lk = (tid & 1) * 8;   // A k offset
    int br = tid >> 1;        // B row (0..95) for tid<192
    int bk2 = (tid & 1) * 8;

    if (LNA) {
        if (tid < CDIM) { gsm[tid] = LNG[tid]; bsm[tid] = LNB[tid]; }
        __syncthreads();
    }

    float acc[8][6];
#pragma unroll
    for (int i = 0; i < 8; i++)
#pragma unroll
        for (int j = 0; j < 6; j++) acc[i][j] = 0.0f;

    float ldA[8], ldB[8];
    int KT = K / BK;

#define G96_LOAD(kt)                                                         \
    {                                                                        \
        const float* ap = A + (size_t)(m0 + lr) * K + (kt) * BK + lk;        \
        *(float4*)&ldA[0] = *(const float4*)ap;                              \
        *(float4*)&ldA[4] = *(const float4*)(ap + 4);                        \
        if (LNA) {                                                           \
            float muv = MU[m0 + lr], rsv = RS[m0 + lr];                      \
            _Pragma("unroll")                                                \
            for (int j = 0; j < 8; j++) {                                    \
                int kk = (kt) * BK + lk + j;                                 \
                ldA[j] = (ldA[j] - muv) * rsv * gsm[kk] + bsm[kk];           \
            }                                                                \
        }                                                                    \
        if (tid < 192) {                                                     \
            const float* bp = B + (size_t)(n0 + br) * K + (kt) * BK + bk2;   \
            *(float4*)&ldB[0] = *(const float4*)bp;                          \
            *(float4*)&ldB[4] = *(const float4*)(bp + 4);                    \
        }                                                                    \
    }

#define G96_STS(bsel)                                                        \
    {                                                                        \
        _Pragma("unroll")                                                    \
        for (int j = 0; j < 8; j++) As[bsel][lk + j][lr] = ldA[j];           \
        if (tid < 192) {                                                     \
            _Pragma("unroll")                                                \
            for (int j = 0; j < 8; j++) Bs[bsel][bk2 + j][br] = ldB[j];      \
        }                                                                    \
    }

    G96_LOAD(0);
    G96_STS(0);
    __syncthreads();

    int buf = 0;
    for (int kt = 0; kt < KT; kt++) {
        if (kt + 1 < KT) G96_LOAD(kt + 1);
#pragma unroll
        for (int k = 0; k < BK; k++) {
            float4 a0 = *(const float4*)&As[buf][k][ty * 4];
            float4 a1 = *(const float4*)&As[buf][k][ty * 4 + 64];
            float a[8] = {a0.x, a0.y, a0.z, a0.w, a1.x, a1.y, a1.z, a1.w};
            float b[6];
#pragma unroll
            for (int j = 0; j < 6; j++) b[j] = Bs[buf][k][tx * 6 + j];
#pragma unroll
            for (int i = 0; i < 8; i++)
#pragma unroll
                for (int j = 0; j < 6; j++) acc[i][j] += a[i] * b[j];
        }
        if (kt + 1 < KT) {
            G96_STS(buf ^ 1);
            __syncthreads();
        }
        buf ^= 1;
    }

    float add = 0.0f;
    float* dst = C;
    if (MODE == 2) {
        if (flag[0]) {
            float gte = 1.0f / (1.0f + expf(-gatep[0]));
            add = (1.0f - gte) * 0.5f;
            dst = Cfast;
        }
    }
#pragma unroll
    for (int i = 0; i < 8; i++) {
        int m = m0 + ty * 4 + (i < 4 ? i : 60 + i);
#pragma unroll
        for (int j = 0; j < 6; j++) {
            int n = n0 + tx * 6 + j;
            float v = acc[i][j];
            if (MODE == 1) {
                C[(size_t)m * ldc + n] = v + bias[n];
            } else {
                dst[(size_t)m * ldc + n] =
                    ex1[(size_t)m * CDIM + n] + v + bias[n] + add;
            }
        }
    }
#undef G96_LOAD
#undef G96_STS
}

// ---------------- fp32 tiled GEMM, 128x128x16 (modes 3,4,5; full path only) --
// SKIP=1: early-exit whole kernel when flag set.
template<int MODE, bool BTRANS, bool BMASK, int SKIP>
__global__ __launch_bounds__(256, 2) void gemm2_k(
    const float* __restrict__ A, const float* __restrict__ B,
    const float* __restrict__ bias, const float* __restrict__ ex1,
    const float* __restrict__ ex2, float* __restrict__ C,
    int M, int N, int K, int ldc, const int* __restrict__ flag)
{
    const int BM = 128, BN = 128, BK = 16;

    int tid = threadIdx.x;
    int m0 = blockIdx.x * BM;
    int n0 = blockIdx.y * BN;
    int tx = tid & 15;
    int ty = tid >> 4;

    if (SKIP == 1) {
        if (flag[0]) return;
    }

    __shared__ __align__(16) float As[2][BK][BM + 4];
    __shared__ __align__(16) float Bs[2][BK][BN + 4];

    int lr = tid >> 1;
    int lk = (tid & 1) * 8;
    int bk = tid >> 4;
    int bn = (tid & 15) * 8;

    float acc[8][8];
#pragma unroll
    for (int i = 0; i < 8; i++)
#pragma unroll
        for (int j = 0; j < 8; j++) acc[i][j] = 0.0f;

    float ldA[8], ldB[8];
    int KT = K / BK;

#define GEMM_LOAD(kt)                                                        \
    {                                                                        \
        const float* ap = A + (size_t)(m0 + lr) * K + (kt) * BK + lk;        \
        *(float4*)&ldA[0] = *(const float4*)ap;                              \
        *(float4*)&ldA[4] = *(const float4*)(ap + 4);                        \
        if (!BTRANS) {                                                       \
            int n = n0 + lr;                                                 \
            if (n < N) {                                                     \
                const float* bp = B + (size_t)n * K + (kt) * BK + lk;        \
                *(float4*)&ldB[0] = *(const float4*)bp;                      \
                *(float4*)&ldB[4] = *(const float4*)(bp + 4);                \
            } else {                                                         \
                _Pragma("unroll")                                            \
                for (int j = 0; j < 8; j++) ldB[j] = 0.0f;                   \
            }                                                                \
            if (BMASK) {                                                     \
                _Pragma("unroll")                                            \
                for (int j = 0; j < 8; j++)                                  \
                    ldB[j] = (ldB[j] > 0.0f) ? 1.0f : 0.0f;                  \
            }                                                                \
        } else {                                                             \
            _Pragma("unroll")                                                \
            for (int j = 0; j < 8; j++) {                                    \
                int n = n0 + bn + j;                                         \
                ldB[j] = (n < N)                                             \
                    ? B[(size_t)((kt) * BK + bk) * N + n] : 0.0f;            \
            }                                                                \
        }                                                                    \
    }

#define GEMM_STS(bsel)                                                       \
    {                                                                        \
        _Pragma("unroll")                                                    \
        for (int j = 0; j < 8; j++) As[bsel][lk + j][lr] = ldA[j];           \
        if (!BTRANS) {                                                       \
            _Pragma("unroll")                                                \
            for (int j = 0; j < 8; j++) Bs[bsel][lk + j][lr] = ldB[j];       \
        } else {                                                             \
            _Pragma("unroll")                                                \
            for (int j = 0; j < 8; j++) Bs[bsel][bk][bn + j] = ldB[j];       \
        }                                                                    \
    }

    GEMM_LOAD(0);
    GEMM_STS(0);
    __syncthreads();

    int buf = 0;
    for (int kt = 0; kt < KT; kt++) {
        if (kt + 1 < KT) GEMM_LOAD(kt + 1);
#pragma unroll
        for (int k = 0; k < BK; k++) {
            float4 a0 = *(const float4*)&As[buf][k][ty * 4];
            float4 a1 = *(const float4*)&As[buf][k][ty * 4 + 64];
            float4 b0 = *(const float4*)&Bs[buf][k][tx * 4];
            float4 b1 = *(const float4*)&Bs[buf][k][tx * 4 + 64];
            float a[8] = {a0.x, a0.y, a0.z, a0.w, a1.x, a1.y, a1.z, a1.w};
            float b[8] = {b0.x, b0.y, b0.z, b0.w, b1.x, b1.y, b1.z, b1.w};
#pragma unroll
            for (int i = 0; i < 8; i++)
#pragma unroll
                for (int j = 0; j < 8; j++) acc[i][j] += a[i] * b[j];
        }
        if (kt + 1 < KT) {
            GEMM_STS(buf ^ 1);
            __syncthreads();
        }
        buf ^= 1;
    }

    float gte = 0.0f;
    if (MODE == 5) gte = 1.0f / (1.0f + expf(-ex2[0]));
#pragma unroll
    for (int i = 0; i < 8; i++) {
        int m = m0 + ty * 4 + (i < 4 ? i : 60 + i);
#pragma unroll
        for (int j = 0; j < 8; j++) {
            int n = n0 + tx * 4 + (j < 4 ? j : 60 + j);
            if (n >= N) continue;
            float v = acc[i][j];
            if (MODE == 3) {
                float y = 1.0f / (1.0f + expf(-(v + bias[n])));
                C[(size_t)m * LITDIM + n]          = logf(fmaxf(y, 1e-6f));
                C[(size_t)m * LITDIM + HIDDIM + n] = logf(fmaxf(1.0f - y, 1e-6f));
            } else if (MODE == 4) {
                C[(size_t)m * ldc + n] = expf(v);
            } else if (MODE == 5) {
                float s = 1.0f / (1.0f + expf(-v));
                C[(size_t)m * ldc + n] = ex1[(size_t)m * CDIM + n] + gte * v + (1.0f - gte) * s;
            }
        }
    }
#undef GEMM_LOAD
#undef GEMM_STS
}

// ---------------- windowed attention, one block per (window, head) -----------
// grid (NWIN, 3), block 128. Round-8 scalar micro-tiles + pair-parallel softmax.
__global__ __launch_bounds__(128) void attn2_kernel(
    const float* __restrict__ qkv, float* __restrict__ ao)
{
    __shared__ __align__(16) float qs[50][44];   // row 49: pad (garbage ok)
    __shared__ __align__(16) float ks[50][44];
    __shared__ __align__(16) float vs[49][44];
    __shared__ float ps[52][53];
    __shared__ int ltab[49];
    __shared__ int otab[49];

    int w  = blockIdx.x;
    int h  = blockIdx.y;
    int b  = w >> 6;
    int wh = (w >> 3) & 7;
    int ww = w & 7;
    int tid = threadIdx.x;

    if (tid < 49) {
        int th = tid / 7, tw = tid % 7;
        int r = (wh * 7 + th + 3) % IMGHW;
        int c = (ww * 7 + tw + 3) % IMGHW;
        ltab[tid] = b * (IMGHW * IMGHW) + r * IMGHW + c;
        int ro = wh * 7 + (th + 3) % 7;          // intra-window inverse roll
        int co = ww * 7 + (tw + 3) % 7;
        otab[tid] = b * (IMGHW * IMGHW) + ro * IMGHW + co;
    }
    __syncthreads();

    // load q/k/v for this head: 49 tokens x 8 d-quads
    for (int i = tid; i < 49 * 8; i += 128) {
        int t = i >> 3, dq = (i & 7) * 4;
        const float* base = qkv + (size_t)ltab[t] * QKVDIM + h * 32 + dq;
        *(float4*)&qs[t][dq] = *(const float4*)base;
        *(float4*)&ks[t][dq] = *(const float4*)(base + 96);
        *(float4*)&vs[t][dq] = *(const float4*)(base + 192);
    }
    __syncthreads();

    const float scale = 0.17677669529663687f;  // 1/sqrt(32)

    // scores: 25x25 grid of 2x2 tiles (pad row 49 read, writes guarded)
    for (int tile = tid; tile < 625; tile += 128) {
        int rp = tile % 25, cp = tile / 25;
        int r0 = rp * 2, c0 = cp * 2;
        float a00 = 0.0f, a01 = 0.0f, a10 = 0.0f, a11 = 0.0f;
#pragma unroll
        for (int dq = 0; dq < 32; dq += 4) {
            float4 qa = *(const float4*)&qs[r0][dq];
            float4 qb = *(const float4*)&qs[r0 + 1][dq];
            float4 ka = *(const float4*)&ks[c0][dq];
            float4 kb = *(const float4*)&ks[c0 + 1][dq];
            a00 += qa.x * ka.x + qa.y * ka.y + qa.z * ka.z + qa.w * ka.w;
            a01 += qa.x * kb.x + qa.y * kb.y + qa.z * kb.z + qa.w * kb.w;
            a10 += qb.x * ka.x + qb.y * ka.y + qb.z * ka.z + qb.w * ka.w;
            a11 += qb.x * kb.x + qb.y * kb.y + qb.z * kb.z + qb.w * kb.w;
        }
        ps[r0][c0] = a00 * scale;
        if (c0 + 1 < 49) ps[r0][c0 + 1] = a01 * scale;
        if (r0 + 1 < 49) {
            ps[r0 + 1][c0] = a10 * scale;
            if (c0 + 1 < 49) ps[r0 + 1][c0 + 1] = a11 * scale;
        }
    }
    __syncthreads();

    // softmax: 2 threads per row, shfl-pair combine
    if (tid < 98) {
        int row = tid >> 1, half = tid & 1;
        int c0 = half ? 25 : 0;
        int c1 = half ? 49 : 25;
        unsigned mask = (tid < 96) ? 0xffffffffu : 0x3u;
        float mx = -1e30f;
        for (int j = c0; j < c1; j++) mx = fmaxf(mx, ps[row][j]);
        mx = fmaxf(mx, __shfl_xor_sync(mask, mx, 1));
        float sum = 0.0f;
        for (int j = c0; j < c1; j++) {
            float e = expf(ps[row][j] - mx);
            ps[row][j] = e;
            sum += e;
        }
        sum += __shfl_xor_sync(mask, sum, 1);
        float inv = 1.0f / sum;
        for (int j = c0; j < c1; j++) ps[row][j] *= inv;
    }
    __syncthreads();

    // AV: 13 token-groups x 8 d-quads = 104 tiles; 4 tokens x 4 dims each
    for (int tile = tid; tile < 104; tile += 128) {
        int tg = tile >> 3, dq = (tile & 7) * 4;
        int t0 = tg * 4;
        float acc[4][4];
#pragma unroll
        for (int i = 0; i < 4; i++)
#pragma unroll
            for (int j = 0; j < 4; j++) acc[i][j] = 0.0f;
        for (int j = 0; j < 49; j++) {
            float4 v4 = *(const float4*)&vs[j][dq];
#pragma unroll
            for (int it = 0; it < 4; it++) {
                float p = ps[t0 + it][j];   // rows 49..51 garbage, never stored
                acc[it][0] += p * v4.x;
                acc[it][1] += p * v4.y;
                acc[it][2] += p * v4.z;
                acc[it][3] += p * v4.w;
            }
        }
#pragma unroll
        for (int it = 0; it < 4; it++) {
            int t = t0 + it;
            if (t < 49) {
                float4 o = {acc[it][0], acc[it][1], acc[it][2], acc[it][3]};
                *(float4*)&ao[(size_t)otab[t] * CDIM + h * 32 + dq] = o;
            }
        }
    }
}

// ---------------- host launcher ----------------------------------------------
extern "C" void kernel_launch(void* const* d_in, const int* in_sizes, int n_in,
                              void* d_out, int out_size)
{
    const float* x       = (const float*)d_in[0];
    const float* n1g     = (const float*)d_in[1];
    const float* n1b     = (const float*)d_in[2];
    const float* qkv_w   = (const float*)d_in[3];
    const float* qkv_b   = (const float*)d_in[4];
    const float* proj_w  = (const float*)d_in[5];
    const float* proj_b  = (const float*)d_in[6];
    const float* n2g     = (const float*)d_in[7];
    const float* n2b     = (const float*)d_in[8];
    const float* fng     = (const float*)d_in[9];
    const float* fnb     = (const float*)d_in[10];
    const float* pin_w   = (const float*)d_in[11];
    const float* pin_b   = (const float*)d_in[12];
    const float* tm_inc  = (const float*)d_in[13];
    const float* tm_out  = (const float*)d_in[14];
    const float* gate    = (const float*)d_in[15];
    float* out           = (float*)d_out;

    float *p_mu, *p_rs, *p_qkv, *p_ao, *p_x1, *p_w, *p_ll, *p_cl;
    int* p_skip;
    cudaGetSymbolAddress((void**)&p_mu,  g_mu);
    cudaGetSymbolAddress((void**)&p_rs,  g_rs);
    cudaGetSymbolAddress((void**)&p_qkv, g_qkv);
    cudaGetSymbolAddress((void**)&p_ao,  g_ao);
    cudaGetSymbolAddress((void**)&p_x1,  g_x1);
    cudaGetSymbolAddress((void**)&p_w,   g_w);
    cudaGetSymbolAddress((void**)&p_ll,  g_ll);
    cudaGetSymbolAddress((void**)&p_cl,  g_cl);
    cudaGetSymbolAddress((void**)&p_skip, g_skip);

    const int MB = NTOK / 128;  // 392

    // 0) guard: decide whether the clause branch is provably negligible
    guard_kernel<<<1, 1024>>>(tm_inc, tm_out, p_skip);

    // 1) LN1 stats (mean/rstd only; LN applied inside the qkv GEMM A-load)
    ln1_stats<<<NTOK / 8, 256>>>(x, p_mu, p_rs);

    // 2) QKV GEMM with fused LN1: (50176 x 96) @ (288 x 96)^T + b
    gemm96_k<1, true><<<dim3(MB, QKVDIM / 96), 256>>>(
        x, qkv_w, qkv_b, nullptr, p_qkv, NTOK, QKVDIM, CDIM, QKVDIM,
        p_mu, p_rs, n1g, n1b, nullptr, nullptr, p_skip);

    // 3) windowed attention: one block per (window, head)
    attn2_kernel<<<dim3(NWIN, 3), 128>>>(p_qkv, p_ao);

    // 4) proj + residual; on fast path writes final output directly
    gemm96_k<2, false><<<dim3(MB, 1), 256>>>(
        p_ao, proj_w, proj_b, x, p_x1, NTOK, CDIM, CDIM, CDIM,
        nullptr, nullptr, nullptr, nullptr, out, gate, p_skip);

    // 5) double layernorm -> g_w   (skipped on fast path)
    ln2_kernel<<<NTOK / 8, 256>>>(p_x1, n2g, n2b, fng, fnb, p_w, p_skip);

    // 6) pin GEMM + sigmoid + log-literals -> g_ll   (skipped on fast path)
    gemm2_k<3, false, false, 1><<<dim3(MB, (HIDDIM + 127) / 128), 256>>>(
        p_w, pin_w, pin_b, nullptr, nullptr, p_ll,
        NTOK, HIDDIM, CDIM, LITDIM, p_skip);

    // 7) clause GEMM, binary mask, exp epilogue -> g_cl (skipped on fast path)
    gemm2_k<4, false, true, 1><<<dim3(MB, 1), 256>>>(
        p_ll, tm_inc, nullptr, nullptr, nullptr, p_cl,
        NTOK, NCLAUSE, LITDIM, NCLAUSE, p_skip);

    // 8) final GEMM: full path only (fast path already wrote out in step 4)
    gemm2_k<5, true, false, 1><<<dim3(MB, 1), 256>>>(
        p_cl, tm_out, nullptr, p_x1, gate, out,
        NTOK, CDIM, NCLAUSE, CDIM, p_skip);

    (void)in_sizes; (void)n_in; (void)out_size;
}

// round 11
// speedup vs baseline: 1.4951x; 1.2021x over previous
#include <cuda_runtime.h>
#include <math.h>
#include <limits.h>

// Problem constants
#define NTOK 50176            // 16 * 56 * 56
#define CDIM 96
#define QKVDIM 288
#define HIDDIM 384
#define LITDIM 768
#define NCLAUSE 128
#define NWIN 1024             // 16 * 8 * 8
#define IMGHW 56
#define LNEPS 1e-5f

// ---------------- scratch (static device arrays; no allocation) -------------
__device__ float g_mu [(size_t)NTOK];
__device__ float g_rs [(size_t)NTOK];
__device__ float g_qkv[(size_t)NTOK * QKVDIM];
__device__ float g_ao [(size_t)NTOK * CDIM];
__device__ float g_x1 [(size_t)NTOK * CDIM];
__device__ float g_w  [(size_t)NTOK * CDIM];
__device__ float g_ll [(size_t)NTOK * LITDIM];
__device__ float g_cl [(size_t)NTOK * NCLAUSE];
__device__ int   g_skip;     // 1 => TM-FFN branch provably ~0, take fast path

// ---------------- helpers ---------------------------------------------------
__device__ __forceinline__ float warp_sum(float v) {
#pragma unroll
    for (int o = 16; o > 0; o >>= 1) v += __shfl_xor_sync(0xffffffffu, v, o);
    return v;
}

__device__ __forceinline__ unsigned f2tf32(float x) {
    unsigned r;
    asm("cvt.rna.tf32.f32 %0, %1;" : "=r"(r) : "f"(x));
    return r;
}

// d += A(16x8) * B(8x8), tf32 operands, f32 accum. Standard m16n8k8 fragments.
__device__ __forceinline__ void mma_tf32(float* d, const unsigned* a,
                                         const unsigned* b) {
    asm("mma.sync.aligned.m16n8k8.row.col.f32.tf32.tf32.f32 "
        "{%0,%1,%2,%3}, {%4,%5,%6,%7}, {%8,%9}, {%0,%1,%2,%3};"
        : "+f"(d[0]), "+f"(d[1]), "+f"(d[2]), "+f"(d[3])
        : "r"(a[0]), "r"(a[1]), "r"(a[2]), "r"(a[3]), "r"(b[0]), "r"(b[1]));
}

// ---------------- guard: is the clause branch provably negligible? ----------
// Any literal pair (j, j+384) with BOTH mask bits set contributes
// log(max(y,eps)) + log(max(1-y,eps)) <= log(1/4) to the clause exponent S,
// so |logits| <= NCLAUSE * max|tm_out| * exp(-1.386 * min_c n_both(c)).
// Bound < 1e-25 => replacing logits by 0 perturbs output < 1e-25: fast path.
__global__ __launch_bounds__(1024) void guard_kernel(
    const float* __restrict__ tm_inc, const float* __restrict__ tm_out,
    int* __restrict__ flag)
{
    __shared__ int   cnt[1024];
    __shared__ int   csum[NCLAUSE];
    __shared__ float mxs[1024];
    int t = threadIdx.x;
    int c = t >> 3, sub = t & 7;      // 8 threads per clause, 48 pairs each
    const float4* rowA = (const float4*)(tm_inc + (size_t)c * LITDIM);
    const float4* rowB = (const float4*)(tm_inc + (size_t)c * LITDIM + HIDDIM);
    int cn = 0;
    int base = sub * 12;              // 12 float4 = 48 floats
#pragma unroll
    for (int q = 0; q < 12; q++) {
        float4 a = rowA[base + q];
        float4 b = rowB[base + q];
        cn += (a.x > 0.0f && b.x > 0.0f) ? 1 : 0;
        cn += (a.y > 0.0f && b.y > 0.0f) ? 1 : 0;
        cn += (a.z > 0.0f && b.z > 0.0f) ? 1 : 0;
        cn += (a.w > 0.0f && b.w > 0.0f) ? 1 : 0;
    }
    cnt[t] = cn;
    float m = 0.0f;
    const float4* to4 = (const float4*)tm_out;   // 12288 floats = 3072 float4
#pragma unroll
    for (int q = 0; q < 3; q++) {
        float4 v = to4[t + q * 1024];
        m = fmaxf(m, fmaxf(fmaxf(fabsf(v.x), fabsf(v.y)),
                           fmaxf(fabsf(v.z), fabsf(v.w))));
    }
    mxs[t] = m;
    __syncthreads();
    if (t < NCLAUSE) {
        int s = 0;
#pragma unroll
        for (int i = 0; i < 8; i++) s += cnt[t * 8 + i];
        csum[t] = s;
    }
    __syncthreads();
    if (t == 0) {
        int mn = INT_MAX;
        for (int i = 0; i < NCLAUSE; i++) mn = (csum[i] < mn) ? csum[i] : mn;
        float M = 0.0f;
        for (int i = 0; i < 1024; i++) M = fmaxf(M, mxs[i]);
        float logbound = logf((float)NCLAUSE * M + 1e-30f) - 1.3862944f * (float)mn;
        flag[0] = (logbound < -57.6f) ? 1 : 0;   // e^-57.6 ~ 1e-25
    }
}

// ---------------- LN1 stats only (mean + rstd per token) ---------------------
__global__ __launch_bounds__(256) void ln1_stats(
    const float* __restrict__ x, float* __restrict__ mu, float* __restrict__ rs)
{
    int warp = (blockIdx.x * blockDim.x + threadIdx.x) >> 5;
    int lane = threadIdx.x & 31;
    if (warp >= NTOK) return;
    size_t base = (size_t)warp * CDIM;
    float v0 = x[base + lane];
    float v1 = x[base + lane + 32];
    float v2 = x[base + lane + 64];
    float mean = warp_sum(v0 + v1 + v2) * (1.0f / CDIM);
    float d0 = v0 - mean, d1 = v1 - mean, d2 = v2 - mean;
    float var = warp_sum(d0 * d0 + d1 * d1 + d2 * d2) * (1.0f / CDIM);
    if (lane == 0) {
        mu[warp] = mean;
        rs[warp] = rsqrtf(var + LNEPS);
    }
}

// double layernorm: w = LN(LN(x1, g2, b2), fg, fb); early-exit on fast path
__global__ __launch_bounds__(256) void ln2_kernel(
    const float* __restrict__ x, const float* __restrict__ g2,
    const float* __restrict__ b2, const float* __restrict__ fg,
    const float* __restrict__ fb, float* __restrict__ y,
    const int* __restrict__ flag)
{
    if (flag[0]) return;
    int warp = (blockIdx.x * blockDim.x + threadIdx.x) >> 5;
    int lane = threadIdx.x & 31;
    if (warp >= NTOK) return;
    size_t base = (size_t)warp * CDIM;
    float v0 = x[base + lane];
    float v1 = x[base + lane + 32];
    float v2 = x[base + lane + 64];
    float mean = warp_sum(v0 + v1 + v2) * (1.0f / CDIM);
    float d0 = v0 - mean, d1 = v1 - mean, d2 = v2 - mean;
    float var = warp_sum(d0 * d0 + d1 * d1 + d2 * d2) * (1.0f / CDIM);
    float rsv = rsqrtf(var + LNEPS);
    float z0 = d0 * rsv * g2[lane]      + b2[lane];
    float z1 = d1 * rsv * g2[lane + 32] + b2[lane + 32];
    float z2 = d2 * rsv * g2[lane + 64] + b2[lane + 64];
    float m2 = warp_sum(z0 + z1 + z2) * (1.0f / CDIM);
    float e0 = z0 - m2, e1 = z1 - m2, e2 = z2 - m2;
    float var2 = warp_sum(e0 * e0 + e1 * e1 + e2 * e2) * (1.0f / CDIM);
    float rs2 = rsqrtf(var2 + LNEPS);
    y[base + lane]      = e0 * rs2 * fg[lane]      + fb[lane];
    y[base + lane + 32] = e1 * rs2 * fg[lane + 32] + fb[lane + 32];
    y[base + lane + 64] = e2 * rs2 * fg[lane + 64] + fb[lane + 64];
}

// ---------------- TF32 tensor-core GEMM (3xTF32: near-fp32 accuracy) ---------
// C[M x N] = A[M x 96] @ B^T (+bias), B is N x 96 row-major. BM=128, BN=96.
// One smem load (K=96 entire), 8 warps, warp tile 32x48, mma m16n8k8.
// 3xTF32 split: a = ah + al, b = bh + bl; d += ah*bh + al*bh + ah*bl.
// LNA: A element = (x - mu[m]) * rs[m] * gamma[k] + beta[k] applied at load.
// MODE 1 (qkv): C = acc + bias[n]
// MODE 2 (proj): full path -> C = ex1 + acc + bias
//                fast path -> Cfast = ex1 + acc + bias + (1-sigmoid(gate))*0.5
#define TC_LDA 100   // row pitch (mod 32 == 4 -> conflict-free frag loads)
#define TC_SMEM ((128 * TC_LDA + 96 * TC_LDA) * 4)

template<int MODE, bool LNA>
__global__ __launch_bounds__(256, 2) void gemmtc_k(
    const float* __restrict__ A, const float* __restrict__ B,
    const float* __restrict__ bias, const float* __restrict__ ex1,
    float* __restrict__ C, int ldc,
    const float* __restrict__ MU, const float* __restrict__ RS,
    const float* __restrict__ LNG, const float* __restrict__ LNB,
    float* __restrict__ Cfast, const float* __restrict__ gatep,
    const int* __restrict__ flag)
{
    extern __shared__ float sm[];
    float* As = sm;                    // [128][TC_LDA]
    float* Bs = sm + 128 * TC_LDA;     // [96][TC_LDA]
    __shared__ float gsm[CDIM], bsm[CDIM], bias_sm[96];

    int tid  = threadIdx.x;
    int warp = tid >> 5;
    int lane = tid & 31;
    int gid  = lane >> 2;      // 0..7
    int tig  = lane & 3;       // 0..3
    int m0 = blockIdx.x * 128;
    int n0 = blockIdx.y * 96;
    int mw = (warp & 3) * 32;  // warp m offset
    int nw = (warp >> 2) * 48; // warp n offset

    if (tid < 96) {
        bias_sm[tid] = bias[n0 + tid];
        if (LNA) { gsm[tid] = LNG[tid]; bsm[tid] = LNB[tid]; }
    }

    // load A tile (128 x 96), LN fused; 2 threads per row, 48 cols each
    {
        int r  = tid >> 1;
        int cb = (tid & 1) * 48;
        const float* ap = A + (size_t)(m0 + r) * CDIM + cb;
        float* as = As + r * TC_LDA + cb;
        if (LNA) {
            __syncthreads();   // gsm/bsm ready
            float muv = MU[m0 + r], rsv = RS[m0 + r];
#pragma unroll
            for (int q = 0; q < 12; q++) {
                float4 v = *(const float4*)(ap + q * 4);
                int k = cb + q * 4;
                v.x = (v.x - muv) * rsv * gsm[k]     + bsm[k];
                v.y = (v.y - muv) * rsv * gsm[k + 1] + bsm[k + 1];
                v.z = (v.z - muv) * rsv * gsm[k + 2] + bsm[k + 2];
                v.w = (v.w - muv) * rsv * gsm[k + 3] + bsm[k + 3];
                *(float4*)(as + q * 4) = v;
            }
        } else {
#pragma unroll
            for (int q = 0; q < 12; q++)
                *(float4*)(as + q * 4) = *(const float4*)(ap + q * 4);
        }
    }
    // load B tile (96 x 96): threads 0..191, 2 per row
    if (tid < 192) {
        int r  = tid >> 1;
        int cb = (tid & 1) * 48;
        const float* bp = B + (size_t)(n0 + r) * CDIM + cb;
        float* bs = Bs + r * TC_LDA + cb;
#pragma unroll
        for (int q = 0; q < 12; q++)
            *(float4*)(bs + q * 4) = *(const float4*)(bp + q * 4);
    }
    __syncthreads();

    float acc[2][6][4];
#pragma unroll
    for (int mt = 0; mt < 2; mt++)
#pragma unroll
        for (int nt = 0; nt < 6; nt++)
#pragma unroll
            for (int i = 0; i < 4; i++) acc[mt][nt][i] = 0.0f;

#pragma unroll 2
    for (int kk = 0; kk < 96; kk += 8) {
        unsigned bh[6][2], bl[6][2];
#pragma unroll
        for (int nt = 0; nt < 6; nt++) {
            int rb = (nw + nt * 8 + gid) * TC_LDA + kk + tig;
            float b0f = Bs[rb];
            float b1f = Bs[rb + 4];
            bh[nt][0] = f2tf32(b0f);
            bl[nt][0] = f2tf32(b0f - __uint_as_float(bh[nt][0]));
            bh[nt][1] = f2tf32(b1f);
            bl[nt][1] = f2tf32(b1f - __uint_as_float(bh[nt][1]));
        }
        unsigned ah[2][4], al[2][4];
#pragma unroll
        for (int mt = 0; mt < 2; mt++) {
            int rb = (mw + mt * 16 + gid) * TC_LDA + kk + tig;
            float a0 = As[rb];
            float a1 = As[rb + 8 * TC_LDA];
            float a2 = As[rb + 4];
            float a3 = As[rb + 8 * TC_LDA + 4];
            ah[mt][0] = f2tf32(a0); al[mt][0] = f2tf32(a0 - __uint_as_float(ah[mt][0]));
            ah[mt][1] = f2tf32(a1); al[mt][1] = f2tf32(a1 - __uint_as_float(ah[mt][1]));
            ah[mt][2] = f2tf32(a2); al[mt][2] = f2tf32(a2 - __uint_as_float(ah[mt][2]));
            ah[mt][3] = f2tf32(a3); al[mt][3] = f2tf32(a3 - __uint_as_float(ah[mt][3]));
        }
#pragma unroll
        for (int mt = 0; mt < 2; mt++)
#pragma unroll
            for (int nt = 0; nt < 6; nt++) {
                mma_tf32(acc[mt][nt], ah[mt], bh[nt]);
                mma_tf32(acc[mt][nt], al[mt], bh[nt]);
                mma_tf32(acc[mt][nt], ah[mt], bl[nt]);
            }
    }

    // epilogue
    float add = 0.0f;
    float* dst = C;
    if (MODE == 2) {
        if (flag[0]) {
            float gte = 1.0f / (1.0f + expf(-gatep[0]));
            add = (1.0f - gte) * 0.5f;
            dst = Cfast;
        }
    }
#pragma unroll
    for (int mt = 0; mt < 2; mt++) {
#pragma unroll
        for (int nt = 0; nt < 6; nt++) {
            int m1 = m0 + mw + mt * 16 + gid;
            int nc = nw + nt * 8 + tig * 2;      // col within 96-slice
            int n1 = n0 + nc;
            float b0 = bias_sm[nc], b1 = bias_sm[nc + 1];
            float* d = acc[mt][nt];
            if (MODE == 1) {
                float2 v0 = {d[0] + b0, d[1] + b1};
                float2 v1 = {d[2] + b0, d[3] + b1};
                *(float2*)&C[(size_t)m1 * ldc + n1] = v0;
                *(float2*)&C[(size_t)(m1 + 8) * ldc + n1] = v1;
            } else {
                float2 e0 = *(const float2*)&ex1[(size_t)m1 * CDIM + n1];
                float2 e1 = *(const float2*)&ex1[(size_t)(m1 + 8) * CDIM + n1];
                float2 v0 = {e0.x + d[0] + b0 + add, e0.y + d[1] + b1 + add};
                float2 v1 = {e1.x + d[2] + b0 + add, e1.y + d[3] + b1 + add};
                *(float2*)&dst[(size_t)m1 * ldc + n1] = v0;
                *(float2*)&dst[(size_t)(m1 + 8) * ldc + n1] = v1;
            }
        }
    }
}

// ---------------- fp32 tiled GEMM, 128x128x16 (modes 3,4,5; full path only) --
// SKIP=1: early-exit whole kernel when flag set.
template<int MODE, bool BTRANS, bool BMASK, int SKIP>
__global__ __launch_bounds__(256, 2) void gemm2_k(
    const float* __restrict__ A, const float* __restrict__ B,
    const float* __restrict__ bias, const float* __restrict__ ex1,
    const float* __restrict__ ex2, float* __restrict__ C,
    int M, int N, int K, int ldc, const int* __restrict__ flag)
{
    const int BM = 128, BN = 128, BK = 16;

    int tid = threadIdx.x;
    int m0 = blockIdx.x * BM;
    int n0 = blockIdx.y * BN;
    int tx = tid & 15;
    int ty = tid >> 4;

    if (SKIP == 1) {
        if (flag[0]) return;
    }

    __shared__ __align__(16) float As[2][BK][BM + 4];
    __shared__ __align__(16) float Bs[2][BK][BN + 4];

    int lr = tid >> 1;
    int lk = (tid & 1) * 8;
    int bk = tid >> 4;
    int bn = (tid & 15) * 8;

    float acc[8][8];
#pragma unroll
    for (int i = 0; i < 8; i++)
#pragma unroll
        for (int j = 0; j < 8; j++) acc[i][j] = 0.0f;

    float ldA[8], ldB[8];
    int KT = K / BK;

#define GEMM_LOAD(kt)                                                        \
    {                                                                        \
        const float* ap = A + (size_t)(m0 + lr) * K + (kt) * BK + lk;        \
        *(float4*)&ldA[0] = *(const float4*)ap;                              \
        *(float4*)&ldA[4] = *(const float4*)(ap + 4);                        \
        if (!BTRANS) {                                                       \
            int n = n0 + lr;                                                 \
            if (n < N) {                                                     \
                const float* bp = B + (size_t)n * K + (kt) * BK + lk;        \
                *(float4*)&ldB[0] = *(const float4*)bp;                      \
                *(float4*)&ldB[4] = *(const float4*)(bp + 4);                \
            } else {                                                         \
                _Pragma("unroll")                                            \
                for (int j = 0; j < 8; j++) ldB[j] = 0.0f;                   \
            }                                                                \
            if (BMASK) {                                                     \
                _Pragma("unroll")                                            \
                for (int j = 0; j < 8; j++)                                  \
                    ldB[j] = (ldB[j] > 0.0f) ? 1.0f : 0.0f;                  \
            }                                                                \
        } else {                                                             \
            _Pragma("unroll")                                                \
            for (int j = 0; j < 8; j++) {                                    \
                int n = n0 + bn + j;                                         \
                ldB[j] = (n < N)                                             \
                    ? B[(size_t)((kt) * BK + bk) * N + n] : 0.0f;            \
            }                                                                \
        }                                                                    \
    }

#define GEMM_STS(bsel)                                                       \
    {                                                                        \
        _Pragma("unroll")                                                    \
        for (int j = 0; j < 8; j++) As[bsel][lk + j][lr] = ldA[j];           \
        if (!BTRANS) {                                                       \
            _Pragma("unroll")                                                \
            for (int j = 0; j < 8; j++) Bs[bsel][lk + j][lr] = ldB[j];       \
        } else {                                                             \
            _Pragma("unroll")                                                \
            for (int j = 0; j < 8; j++) Bs[bsel][bk][bn + j] = ldB[j];       \
        }                                                                    \
    }

    GEMM_LOAD(0);
    GEMM_STS(0);
    __syncthreads();

    int buf = 0;
    for (int kt = 0; kt < KT; kt++) {
        if (kt + 1 < KT) GEMM_LOAD(kt + 1);
#pragma unroll
        for (int k = 0; k < BK; k++) {
            float4 a0 = *(const float4*)&As[buf][k][ty * 4];
            float4 a1 = *(const float4*)&As[buf][k][ty * 4 + 64];
            float4 b0 = *(const float4*)&Bs[buf][k][tx * 4];
            float4 b1 = *(const float4*)&Bs[buf][k][tx * 4 + 64];
            float a[8] = {a0.x, a0.y, a0.z, a0.w, a1.x, a1.y, a1.z, a1.w};
            float b[8] = {b0.x, b0.y, b0.z, b0.w, b1.x, b1.y, b1.z, b1.w};
#pragma unroll
            for (int i = 0; i < 8; i++)
#pragma unroll
                for (int j = 0; j < 8; j++) acc[i][j] += a[i] * b[j];
        }
        if (kt + 1 < KT) {
            GEMM_STS(buf ^ 1);
            __syncthreads();
        }
        buf ^= 1;
    }

    float gte = 0.0f;
    if (MODE == 5) gte = 1.0f / (1.0f + expf(-ex2[0]));
#pragma unroll
    for (int i = 0; i < 8; i++) {
        int m = m0 + ty * 4 + (i < 4 ? i : 60 + i);
#pragma unroll
        for (int j = 0; j < 8; j++) {
            int n = n0 + tx * 4 + (j < 4 ? j : 60 + j);
            if (n >= N) continue;
            float v = acc[i][j];
            if (MODE == 3) {
                float y = 1.0f / (1.0f + expf(-(v + bias[n])));
                C[(size_t)m * LITDIM + n]          = logf(fmaxf(y, 1e-6f));
                C[(size_t)m * LITDIM + HIDDIM + n] = logf(fmaxf(1.0f - y, 1e-6f));
            } else if (MODE == 4) {
                C[(size_t)m * ldc + n] = expf(v);
            } else if (MODE == 5) {
                float s = 1.0f / (1.0f + expf(-v));
                C[(size_t)m * ldc + n] = ex1[(size_t)m * CDIM + n] + gte * v + (1.0f - gte) * s;
            }
        }
    }
#undef GEMM_LOAD
#undef GEMM_STS
}

// ---------------- windowed attention, one block per (window, head) -----------
// grid (NWIN, 3), block 128. Scalar 4x4 score micro-tiles (2 B/FMA from smem).
__global__ __launch_bounds__(128) void attn2_kernel(
    const float* __restrict__ qkv, float* __restrict__ ao)
{
    __shared__ __align__(16) float qs[52][44];   // rows 49..51: pad (garbage ok)
    __shared__ __align__(16) float ks[52][44];
    __shared__ __align__(16) float vs[49][44];
    __shared__ float ps[52][53];
    __shared__ int ltab[49];
    __shared__ int otab[49];

    int w  = blockIdx.x;
    int h  = blockIdx.y;
    int b  = w >> 6;
    int wh = (w >> 3) & 7;
    int ww = w & 7;
    int tid = threadIdx.x;

    if (tid < 49) {
        int th = tid / 7, tw = tid % 7;
        int r = (wh * 7 + th + 3) % IMGHW;
        int c = (ww * 7 + tw + 3) % IMGHW;
        ltab[tid] = b * (IMGHW * IMGHW) + r * IMGHW + c;
        int ro = wh * 7 + (th + 3) % 7;          // intra-window inverse roll
        int co = ww * 7 + (tw + 3) % 7;
        otab[tid] = b * (IMGHW * IMGHW) + ro * IMGHW + co;
    }
    __syncthreads();

    // load q/k/v for this head: 49 tokens x 8 d-quads
    for (int i = tid; i < 49 * 8; i += 128) {
        int t = i >> 3, dq = (i & 7) * 4;
        const float* base = qkv + (size_t)ltab[t] * QKVDIM + h * 32 + dq;
        *(float4*)&qs[t][dq] = *(const float4*)base;
        *(float4*)&ks[t][dq] = *(const float4*)(base + 96);
        *(float4*)&vs[t][dq] = *(const float4*)(base + 192);
    }
    __syncthreads();

    const float scale = 0.17677669529663687f;  // 1/sqrt(32)

    // scores: 13x13 grid of 4x4 tiles (pad rows read, writes guarded)
    for (int tile = tid; tile < 169; tile += 128) {
        int rp = tile % 13, cp = tile / 13;
        int r0 = rp * 4, c0 = cp * 4;
        float a[4][4];
#pragma unroll
        for (int i = 0; i < 4; i++)
#pragma unroll
            for (int j = 0; j < 4; j++) a[i][j] = 0.0f;
#pragma unroll
        for (int dq = 0; dq < 32; dq += 4) {
            float4 k0 = *(const float4*)&ks[c0][dq];
            float4 k1 = *(const float4*)&ks[c0 + 1][dq];
            float4 k2 = *(const float4*)&ks[c0 + 2][dq];
            float4 k3 = *(const float4*)&ks[c0 + 3][dq];
#pragma unroll
            for (int i = 0; i < 4; i++) {
                float4 q = *(const float4*)&qs[r0 + i][dq];
                a[i][0] += q.x * k0.x + q.y * k0.y + q.z * k0.z + q.w * k0.w;
                a[i][1] += q.x * k1.x + q.y * k1.y + q.z * k1.z + q.w * k1.w;
                a[i][2] += q.x * k2.x + q.y * k2.y + q.z * k2.z + q.w * k2.w;
                a[i][3] += q.x * k3.x + q.y * k3.y + q.z * k3.z + q.w * k3.w;
            }
        }
#pragma unroll
        for (int i = 0; i < 4; i++) {
            if (r0 + i >= 49) continue;
#pragma unroll
            for (int j = 0; j < 4; j++)
                if (c0 + j < 49) ps[r0 + i][c0 + j] = a[i][j] * scale;
        }
    }
    __syncthreads();

    // softmax: 2 threads per row, shfl-pair combine
    if (tid < 98) {
        int row = tid >> 1, half = tid & 1;
        int c0 = half ? 25 : 0;
        int c1 = half ? 49 : 25;
        unsigned mask = (tid < 96) ? 0xffffffffu : 0x3u;
        float mx = -1e30f;
        for (int j = c0; j < c1; j++) mx = fmaxf(mx, ps[row][j]);
        mx = fmaxf(mx, __shfl_xor_sync(mask, mx, 1));
        float sum = 0.0f;
        for (int j = c0; j < c1; j++) {
            float e = expf(ps[row][j] - mx);
            ps[row][j] = e;
            sum += e;
        }
        sum += __shfl_xor_sync(mask, sum, 1);
        float inv = 1.0f / sum;
        for (int j = c0; j < c1; j++) ps[row][j] *= inv;
    }
    __syncthreads();

    // AV: 13 token-groups x 8 d-quads = 104 tiles; 4 tokens x 4 dims each
    for (int tile = tid; tile < 104; tile += 128) {
        int tg = tile >> 3, dq = (tile & 7) * 4;
        int t0 = tg * 4;
        float acc[4][4];
#pragma unroll
        for (int i = 0; i < 4; i++)
#pragma unroll
            for (int j = 0; j < 4; j++) acc[i][j] = 0.0f;
        for (int j = 0; j < 49; j++) {
            float4 v4 = *(const float4*)&vs[j][dq];
#pragma unroll
            for (int it = 0; it < 4; it++) {
                float p = ps[t0 + it][j];   // rows 49..51 garbage, never stored
                acc[it][0] += p * v4.x;
                acc[it][1] += p * v4.y;
                acc[it][2] += p * v4.z;
                acc[it][3] += p * v4.w;
            }
        }
#pragma unroll
        for (int it = 0; it < 4; it++) {
            int t = t0 + it;
            if (t < 49) {
                float4 o = {acc[it][0], acc[it][1], acc[it][2], acc[it][3]};
                *(float4*)&ao[(size_t)otab[t] * CDIM + h * 32 + dq] = o;
            }
        }
    }
}

// ---------------- host launcher ----------------------------------------------
extern "C" void kernel_launch(void* const* d_in, const int* in_sizes, int n_in,
                              void* d_out, int out_size)
{
    const float* x       = (const float*)d_in[0];
    const float* n1g     = (const float*)d_in[1];
    const float* n1b     = (const float*)d_in[2];
    const float* qkv_w   = (const float*)d_in[3];
    const float* qkv_b   = (const float*)d_in[4];
    const float* proj_w  = (const float*)d_in[5];
    const float* proj_b  = (const float*)d_in[6];
    const float* n2g     = (const float*)d_in[7];
    const float* n2b     = (const float*)d_in[8];
    const float* fng     = (const float*)d_in[9];
    const float* fnb     = (const float*)d_in[10];
    const float* pin_w   = (const float*)d_in[11];
    const float* pin_b   = (const float*)d_in[12];
    const float* tm_inc  = (const float*)d_in[13];
    const float* tm_out  = (const float*)d_in[14];
    const float* gate    = (const float*)d_in[15];
    float* out           = (float*)d_out;

    float *p_mu, *p_rs, *p_qkv, *p_ao, *p_x1, *p_w, *p_ll, *p_cl;
    int* p_skip;
    cudaGetSymbolAddress((void**)&p_mu,  g_mu);
    cudaGetSymbolAddress((void**)&p_rs,  g_rs);
    cudaGetSymbolAddress((void**)&p_qkv, g_qkv);
    cudaGetSymbolAddress((void**)&p_ao,  g_ao);
    cudaGetSymbolAddress((void**)&p_x1,  g_x1);
    cudaGetSymbolAddress((void**)&p_w,   g_w);
    cudaGetSymbolAddress((void**)&p_ll,  g_ll);
    cudaGetSymbolAddress((void**)&p_cl,  g_cl);
    cudaGetSymbolAddress((void**)&p_skip, g_skip);

    // opt-in dynamic smem for the TC GEMM (>48KB); idempotent, not captured
    static bool attr_done = false;
    if (!attr_done) {
        cudaFuncSetAttribute(gemmtc_k<1, true>,
                             cudaFuncAttributeMaxDynamicSharedMemorySize, TC_SMEM);
        cudaFuncSetAttribute(gemmtc_k<2, false>,
                             cudaFuncAttributeMaxDynamicSharedMemorySize, TC_SMEM);
        attr_done = true;
    }

    const int MB = NTOK / 128;  // 392

    // 0) guard: decide whether the clause branch is provably negligible
    guard_kernel<<<1, 1024>>>(tm_inc, tm_out, p_skip);

    // 1) LN1 stats (mean/rstd only; LN applied inside the qkv GEMM A-load)
    ln1_stats<<<NTOK / 8, 256>>>(x, p_mu, p_rs);

    // 2) QKV GEMM (tensor cores, 3xTF32) with fused LN1
    gemmtc_k<1, true><<<dim3(MB, QKVDIM / 96), 256, TC_SMEM>>>(
        x, qkv_w, qkv_b, nullptr, p_qkv, QKVDIM,
        p_mu, p_rs, n1g, n1b, nullptr, nullptr, p_skip);

    // 3) windowed attention: one block per (window, head)
    attn2_kernel<<<dim3(NWIN, 3), 128>>>(p_qkv, p_ao);

    // 4) proj + residual (tensor cores); fast path writes final output
    gemmtc_k<2, false><<<dim3(MB, 1), 256, TC_SMEM>>>(
        p_ao, proj_w, proj_b, x, p_x1, CDIM,
        nullptr, nullptr, nullptr, nullptr, out, gate, p_skip);

    // 5) double layernorm -> g_w   (skipped on fast path)
    ln2_kernel<<<NTOK / 8, 256>>>(p_x1, n2g, n2b, fng, fnb, p_w, p_skip);

    // 6) pin GEMM + sigmoid + log-literals -> g_ll   (skipped on fast path)
    gemm2_k<3, false, false, 1><<<dim3(MB, (HIDDIM + 127) / 128), 256>>>(
        p_w, pin_w, pin_b, nullptr, nullptr, p_ll,
        NTOK, HIDDIM, CDIM, LITDIM, p_skip);

    // 7) clause GEMM, binary mask, exp epilogue -> g_cl (skipped on fast path)
    gemm2_k<4, false, true, 1><<<dim3(MB, 1), 256>>>(
        p_ll, tm_inc, nullptr, nullptr, nullptr, p_cl,
        NTOK, NCLAUSE, LITDIM, NCLAUSE, p_skip);

    // 8) final GEMM: full path only (fast path already wrote out in step 4)
    gemm2_k<5, true, false, 1><<<dim3(MB, 1), 256>>>(
        p_cl, tm_out, nullptr, p_x1, gate, out,
        NTOK, CDIM, NCLAUSE, CDIM, p_skip);

    (void)in_sizes; (void)n_in; (void)out_size;
}

// round 12
// speedup vs baseline: 1.6820x; 1.1250x over previous
#include <cuda_runtime.h>
#include <math.h>
#include <limits.h>

// Problem constants
#define NTOK 50176            // 16 * 56 * 56
#define CDIM 96
#define QKVDIM 288
#define HIDDIM 384
#define LITDIM 768
#define NCLAUSE 128
#define NWIN 1024             // 16 * 8 * 8
#define IMGHW 56
#define LNEPS 1e-5f

// ---------------- scratch (static device arrays; no allocation) -------------
__device__ float g_mu [(size_t)NTOK];
__device__ float g_rs [(size_t)NTOK];
__device__ float g_qkv[(size_t)NTOK * QKVDIM];
__device__ float g_ao [(size_t)NTOK * CDIM];
__device__ float g_x1 [(size_t)NTOK * CDIM];
__device__ float g_w  [(size_t)NTOK * CDIM];
__device__ float g_ll [(size_t)NTOK * LITDIM];
__device__ float g_cl [(size_t)NTOK * NCLAUSE];
__device__ int   g_skip;     // 1 => TM-FFN branch provably ~0, take fast path

// ---------------- helpers ---------------------------------------------------
__device__ __forceinline__ float warp_sum(float v) {
#pragma unroll
    for (int o = 16; o > 0; o >>= 1) v += __shfl_xor_sync(0xffffffffu, v, o);
    return v;
}

__device__ __forceinline__ unsigned f2tf32(float x) {
    unsigned r;
    asm("cvt.rna.tf32.f32 %0, %1;" : "=r"(r) : "f"(x));
    return r;
}

// d += A(16x8) * B(8x8), tf32 operands, f32 accum. Standard m16n8k8 fragments.
__device__ __forceinline__ void mma_tf32(float* d, const unsigned* a,
                                         const unsigned* b) {
    asm("mma.sync.aligned.m16n8k8.row.col.f32.tf32.tf32.f32 "
        "{%0,%1,%2,%3}, {%4,%5,%6,%7}, {%8,%9}, {%0,%1,%2,%3};"
        : "+f"(d[0]), "+f"(d[1]), "+f"(d[2]), "+f"(d[3])
        : "r"(a[0]), "r"(a[1]), "r"(a[2]), "r"(a[3]), "r"(b[0]), "r"(b[1]));
}

#define SPLIT2(hi, lo, x) { hi = f2tf32(x); lo = f2tf32((x) - __uint_as_float(hi)); }

// ---------------- guard: is the clause branch provably negligible? ----------
// Any literal pair (j, j+384) with BOTH mask bits set contributes
// log(max(y,eps)) + log(max(1-y,eps)) <= log(1/4) to the clause exponent S,
// so |logits| <= NCLAUSE * max|tm_out| * exp(-1.386 * min_c n_both(c)).
// Bound < 1e-25 => replacing logits by 0 perturbs output < 1e-25: fast path.
__global__ __launch_bounds__(1024) void guard_kernel(
    const float* __restrict__ tm_inc, const float* __restrict__ tm_out,
    int* __restrict__ flag)
{
    __shared__ int   cnt[1024];
    __shared__ int   csum[NCLAUSE];
    __shared__ float mxs[1024];
    int t = threadIdx.x;
    int c = t >> 3, sub = t & 7;      // 8 threads per clause, 48 pairs each
    const float4* rowA = (const float4*)(tm_inc + (size_t)c * LITDIM);
    const float4* rowB = (const float4*)(tm_inc + (size_t)c * LITDIM + HIDDIM);
    int cn = 0;
    int base = sub * 12;              // 12 float4 = 48 floats
#pragma unroll
    for (int q = 0; q < 12; q++) {
        float4 a = rowA[base + q];
        float4 b = rowB[base + q];
        cn += (a.x > 0.0f && b.x > 0.0f) ? 1 : 0;
        cn += (a.y > 0.0f && b.y > 0.0f) ? 1 : 0;
        cn += (a.z > 0.0f && b.z > 0.0f) ? 1 : 0;
        cn += (a.w > 0.0f && b.w > 0.0f) ? 1 : 0;
    }
    cnt[t] = cn;
    float m = 0.0f;
    const float4* to4 = (const float4*)tm_out;   // 12288 floats = 3072 float4
#pragma unroll
    for (int q = 0; q < 3; q++) {
        float4 v = to4[t + q * 1024];
        m = fmaxf(m, fmaxf(fmaxf(fabsf(v.x), fabsf(v.y)),
                           fmaxf(fabsf(v.z), fabsf(v.w))));
    }
    mxs[t] = m;
    __syncthreads();
    if (t < NCLAUSE) {
        int s = 0;
#pragma unroll
        for (int i = 0; i < 8; i++) s += cnt[t * 8 + i];
        csum[t] = s;
    }
    __syncthreads();
    if (t == 0) {
        int mn = INT_MAX;
        for (int i = 0; i < NCLAUSE; i++) mn = (csum[i] < mn) ? csum[i] : mn;
        float M = 0.0f;
        for (int i = 0; i < 1024; i++) M = fmaxf(M, mxs[i]);
        float logbound = logf((float)NCLAUSE * M + 1e-30f) - 1.3862944f * (float)mn;
        flag[0] = (logbound < -57.6f) ? 1 : 0;   // e^-57.6 ~ 1e-25
    }
}

// ---------------- LN1 stats only (mean + rstd per token) ---------------------
__global__ __launch_bounds__(256) void ln1_stats(
    const float* __restrict__ x, float* __restrict__ mu, float* __restrict__ rs)
{
    int warp = (blockIdx.x * blockDim.x + threadIdx.x) >> 5;
    int lane = threadIdx.x & 31;
    if (warp >= NTOK) return;
    size_t base = (size_t)warp * CDIM;
    float v0 = x[base + lane];
    float v1 = x[base + lane + 32];
    float v2 = x[base + lane + 64];
    float mean = warp_sum(v0 + v1 + v2) * (1.0f / CDIM);
    float d0 = v0 - mean, d1 = v1 - mean, d2 = v2 - mean;
    float var = warp_sum(d0 * d0 + d1 * d1 + d2 * d2) * (1.0f / CDIM);
    if (lane == 0) {
        mu[warp] = mean;
        rs[warp] = rsqrtf(var + LNEPS);
    }
}

// double layernorm: w = LN(LN(x1, g2, b2), fg, fb); early-exit on fast path
__global__ __launch_bounds__(256) void ln2_kernel(
    const float* __restrict__ x, const float* __restrict__ g2,
    const float* __restrict__ b2, const float* __restrict__ fg,
    const float* __restrict__ fb, float* __restrict__ y,
    const int* __restrict__ flag)
{
    if (flag[0]) return;
    int warp = (blockIdx.x * blockDim.x + threadIdx.x) >> 5;
    int lane = threadIdx.x & 31;
    if (warp >= NTOK) return;
    size_t base = (size_t)warp * CDIM;
    float v0 = x[base + lane];
    float v1 = x[base + lane + 32];
    float v2 = x[base + lane + 64];
    float mean = warp_sum(v0 + v1 + v2) * (1.0f / CDIM);
    float d0 = v0 - mean, d1 = v1 - mean, d2 = v2 - mean;
    float var = warp_sum(d0 * d0 + d1 * d1 + d2 * d2) * (1.0f / CDIM);
    float rsv = rsqrtf(var + LNEPS);
    float z0 = d0 * rsv * g2[lane]      + b2[lane];
    float z1 = d1 * rsv * g2[lane + 32] + b2[lane + 32];
    float z2 = d2 * rsv * g2[lane + 64] + b2[lane + 64];
    float m2 = warp_sum(z0 + z1 + z2) * (1.0f / CDIM);
    float e0 = z0 - m2, e1 = z1 - m2, e2 = z2 - m2;
    float var2 = warp_sum(e0 * e0 + e1 * e1 + e2 * e2) * (1.0f / CDIM);
    float rs2 = rsqrtf(var2 + LNEPS);
    y[base + lane]      = e0 * rs2 * fg[lane]      + fb[lane];
    y[base + lane + 32] = e1 * rs2 * fg[lane + 32] + fb[lane + 32];
    y[base + lane + 64] = e2 * rs2 * fg[lane + 64] + fb[lane + 64];
}

// ---------------- TF32 tensor-core GEMM (3xTF32: near-fp32 accuracy) ---------
// C[M x N] = A[M x 96] @ B^T (+bias), B is N x 96 row-major. BM=128, BN=96.
#define TC_LDA 100   // row pitch (mod 32 == 4 -> conflict-free frag loads)
#define TC_SMEM ((128 * TC_LDA + 96 * TC_LDA) * 4)

template<int MODE, bool LNA>
__global__ __launch_bounds__(256, 2) void gemmtc_k(
    const float* __restrict__ A, const float* __restrict__ B,
    const float* __restrict__ bias, const float* __restrict__ ex1,
    float* __restrict__ C, int ldc,
    const float* __restrict__ MU, const float* __restrict__ RS,
    const float* __restrict__ LNG, const float* __restrict__ LNB,
    float* __restrict__ Cfast, const float* __restrict__ gatep,
    const int* __restrict__ flag)
{
    extern __shared__ float sm[];
    float* As = sm;                    // [128][TC_LDA]
    float* Bs = sm + 128 * TC_LDA;     // [96][TC_LDA]
    __shared__ float gsm[CDIM], bsm[CDIM], bias_sm[96];

    int tid  = threadIdx.x;
    int warp = tid >> 5;
    int lane = tid & 31;
    int gid  = lane >> 2;      // 0..7
    int tig  = lane & 3;       // 0..3
    int m0 = blockIdx.x * 128;
    int n0 = blockIdx.y * 96;
    int mw = (warp & 3) * 32;  // warp m offset
    int nw = (warp >> 2) * 48; // warp n offset

    if (tid < 96) {
        bias_sm[tid] = bias[n0 + tid];
        if (LNA) { gsm[tid] = LNG[tid]; bsm[tid] = LNB[tid]; }
    }

    // load A tile (128 x 96), LN fused; 2 threads per row, 48 cols each
    {
        int r  = tid >> 1;
        int cb = (tid & 1) * 48;
        const float* ap = A + (size_t)(m0 + r) * CDIM + cb;
        float* as = As + r * TC_LDA + cb;
        if (LNA) {
            __syncthreads();   // gsm/bsm ready
            float muv = MU[m0 + r], rsv = RS[m0 + r];
#pragma unroll
            for (int q = 0; q < 12; q++) {
                float4 v = *(const float4*)(ap + q * 4);
                int k = cb + q * 4;
                v.x = (v.x - muv) * rsv * gsm[k]     + bsm[k];
                v.y = (v.y - muv) * rsv * gsm[k + 1] + bsm[k + 1];
                v.z = (v.z - muv) * rsv * gsm[k + 2] + bsm[k + 2];
                v.w = (v.w - muv) * rsv * gsm[k + 3] + bsm[k + 3];
                *(float4*)(as + q * 4) = v;
            }
        } else {
#pragma unroll
            for (int q = 0; q < 12; q++)
                *(float4*)(as + q * 4) = *(const float4*)(ap + q * 4);
        }
    }
    // load B tile (96 x 96): threads 0..191, 2 per row
    if (tid < 192) {
        int r  = tid >> 1;
        int cb = (tid & 1) * 48;
        const float* bp = B + (size_t)(n0 + r) * CDIM + cb;
        float* bs = Bs + r * TC_LDA + cb;
#pragma unroll
        for (int q = 0; q < 12; q++)
            *(float4*)(bs + q * 4) = *(const float4*)(bp + q * 4);
    }
    __syncthreads();

    float acc[2][6][4];
#pragma unroll
    for (int mt = 0; mt < 2; mt++)
#pragma unroll
        for (int nt = 0; nt < 6; nt++)
#pragma unroll
            for (int i = 0; i < 4; i++) acc[mt][nt][i] = 0.0f;

#pragma unroll 2
    for (int kk = 0; kk < 96; kk += 8) {
        unsigned bh[6][2], bl[6][2];
#pragma unroll
        for (int nt = 0; nt < 6; nt++) {
            int rb = (nw + nt * 8 + gid) * TC_LDA + kk + tig;
            float b0f = Bs[rb];
            float b1f = Bs[rb + 4];
            SPLIT2(bh[nt][0], bl[nt][0], b0f);
            SPLIT2(bh[nt][1], bl[nt][1], b1f);
        }
        unsigned ah[2][4], al[2][4];
#pragma unroll
        for (int mt = 0; mt < 2; mt++) {
            int rb = (mw + mt * 16 + gid) * TC_LDA + kk + tig;
            float a0 = As[rb];
            float a1 = As[rb + 8 * TC_LDA];
            float a2 = As[rb + 4];
            float a3 = As[rb + 8 * TC_LDA + 4];
            SPLIT2(ah[mt][0], al[mt][0], a0);
            SPLIT2(ah[mt][1], al[mt][1], a1);
            SPLIT2(ah[mt][2], al[mt][2], a2);
            SPLIT2(ah[mt][3], al[mt][3], a3);
        }
#pragma unroll
        for (int mt = 0; mt < 2; mt++)
#pragma unroll
            for (int nt = 0; nt < 6; nt++) {
                mma_tf32(acc[mt][nt], ah[mt], bh[nt]);
                mma_tf32(acc[mt][nt], al[mt], bh[nt]);
                mma_tf32(acc[mt][nt], ah[mt], bl[nt]);
            }
    }

    // epilogue
    float add = 0.0f;
    float* dst = C;
    if (MODE == 2) {
        if (flag[0]) {
            float gte = 1.0f / (1.0f + expf(-gatep[0]));
            add = (1.0f - gte) * 0.5f;
            dst = Cfast;
        }
    }
#pragma unroll
    for (int mt = 0; mt < 2; mt++) {
#pragma unroll
        for (int nt = 0; nt < 6; nt++) {
            int m1 = m0 + mw + mt * 16 + gid;
            int nc = nw + nt * 8 + tig * 2;      // col within 96-slice
            int n1 = n0 + nc;
            float b0 = bias_sm[nc], b1 = bias_sm[nc + 1];
            float* d = acc[mt][nt];
            if (MODE == 1) {
                float2 v0 = {d[0] + b0, d[1] + b1};
                float2 v1 = {d[2] + b0, d[3] + b1};
                *(float2*)&C[(size_t)m1 * ldc + n1] = v0;
                *(float2*)&C[(size_t)(m1 + 8) * ldc + n1] = v1;
            } else {
                float2 e0 = *(const float2*)&ex1[(size_t)m1 * CDIM + n1];
                float2 e1 = *(const float2*)&ex1[(size_t)(m1 + 8) * CDIM + n1];
                float2 v0 = {e0.x + d[0] + b0 + add, e0.y + d[1] + b1 + add};
                float2 v1 = {e1.x + d[2] + b0 + add, e1.y + d[3] + b1 + add};
                *(float2*)&dst[(size_t)m1 * ldc + n1] = v0;
                *(float2*)&dst[(size_t)(m1 + 8) * ldc + n1] = v1;
            }
        }
    }
}

// ---------------- fp32 tiled GEMM, 128x128x16 (modes 3,4,5; full path only) --
// SKIP=1: early-exit whole kernel when flag set.
template<int MODE, bool BTRANS, bool BMASK, int SKIP>
__global__ __launch_bounds__(256, 2) void gemm2_k(
    const float* __restrict__ A, const float* __restrict__ B,
    const float* __restrict__ bias, const float* __restrict__ ex1,
    const float* __restrict__ ex2, float* __restrict__ C,
    int M, int N, int K, int ldc, const int* __restrict__ flag)
{
    const int BM = 128, BN = 128, BK = 16;

    int tid = threadIdx.x;
    int m0 = blockIdx.x * BM;
    int n0 = blockIdx.y * BN;
    int tx = tid & 15;
    int ty = tid >> 4;

    if (SKIP == 1) {
        if (flag[0]) return;
    }

    __shared__ __align__(16) float As[2][BK][BM + 4];
    __shared__ __align__(16) float Bs[2][BK][BN + 4];

    int lr = tid >> 1;
    int lk = (tid & 1) * 8;
    int bk = tid >> 4;
    int bn = (tid & 15) * 8;

    float acc[8][8];
#pragma unroll
    for (int i = 0; i < 8; i++)
#pragma unroll
        for (int j = 0; j < 8; j++) acc[i][j] = 0.0f;

    float ldA[8], ldB[8];
    int KT = K / BK;

#define GEMM_LOAD(kt)                                                        \
    {                                                                        \
        const float* ap = A + (size_t)(m0 + lr) * K + (kt) * BK + lk;        \
        *(float4*)&ldA[0] = *(const float4*)ap;                              \
        *(float4*)&ldA[4] = *(const float4*)(ap + 4);                        \
        if (!BTRANS) {                                                       \
            int n = n0 + lr;                                                 \
            if (n < N) {                                                     \
                const float* bp = B + (size_t)n * K + (kt) * BK + lk;        \
                *(float4*)&ldB[0] = *(const float4*)bp;                      \
                *(float4*)&ldB[4] = *(const float4*)(bp + 4);                \
            } else {                                                         \
                _Pragma("unroll")                                            \
                for (int j = 0; j < 8; j++) ldB[j] = 0.0f;                   \
            }                                                                \
            if (BMASK) {                                                     \
                _Pragma("unroll")                                            \
                for (int j = 0; j < 8; j++)                                  \
                    ldB[j] = (ldB[j] > 0.0f) ? 1.0f : 0.0f;                  \
            }                                                                \
        } else {                                                             \
            _Pragma("unroll")                                                \
            for (int j = 0; j < 8; j++) {                                    \
                int n = n0 + bn + j;                                         \
                ldB[j] = (n < N)                                             \
                    ? B[(size_t)((kt) * BK + bk) * N + n] : 0.0f;            \
            }                                                                \
        }                                                                    \
    }

#define GEMM_STS(bsel)                                                       \
    {                                                                        \
        _Pragma("unroll")                                                    \
        for (int j = 0; j < 8; j++) As[bsel][lk + j][lr] = ldA[j];           \
        if (!BTRANS) {                                                       \
            _Pragma("unroll")                                                \
            for (int j = 0; j < 8; j++) Bs[bsel][lk + j][lr] = ldB[j];       \
        } else {                                                             \
            _Pragma("unroll")                                                \
            for (int j = 0; j < 8; j++) Bs[bsel][bk][bn + j] = ldB[j];       \
        }                                                                    \
    }

    GEMM_LOAD(0);
    GEMM_STS(0);
    __syncthreads();

    int buf = 0;
    for (int kt = 0; kt < KT; kt++) {
        if (kt + 1 < KT) GEMM_LOAD(kt + 1);
#pragma unroll
        for (int k = 0; k < BK; k++) {
            float4 a0 = *(const float4*)&As[buf][k][ty * 4];
            float4 a1 = *(const float4*)&As[buf][k][ty * 4 + 64];
            float4 b0 = *(const float4*)&Bs[buf][k][tx * 4];
            float4 b1 = *(const float4*)&Bs[buf][k][tx * 4 + 64];
            float a[8] = {a0.x, a0.y, a0.z, a0.w, a1.x, a1.y, a1.z, a1.w};
            float b[8] = {b0.x, b0.y, b0.z, b0.w, b1.x, b1.y, b1.z, b1.w};
#pragma unroll
            for (int i = 0; i < 8; i++)
#pragma unroll
                for (int j = 0; j < 8; j++) acc[i][j] += a[i] * b[j];
        }
        if (kt + 1 < KT) {
            GEMM_STS(buf ^ 1);
            __syncthreads();
        }
        buf ^= 1;
    }

    float gte = 0.0f;
    if (MODE == 5) gte = 1.0f / (1.0f + expf(-ex2[0]));
#pragma unroll
    for (int i = 0; i < 8; i++) {
        int m = m0 + ty * 4 + (i < 4 ? i : 60 + i);
#pragma unroll
        for (int j = 0; j < 8; j++) {
            int n = n0 + tx * 4 + (j < 4 ? j : 60 + j);
            if (n >= N) continue;
            float v = acc[i][j];
            if (MODE == 3) {
                float y = 1.0f / (1.0f + expf(-(v + bias[n])));
                C[(size_t)m * LITDIM + n]          = logf(fmaxf(y, 1e-6f));
                C[(size_t)m * LITDIM + HIDDIM + n] = logf(fmaxf(1.0f - y, 1e-6f));
            } else if (MODE == 4) {
                C[(size_t)m * ldc + n] = expf(v);
            } else if (MODE == 5) {
                float s = 1.0f / (1.0f + expf(-v));
                C[(size_t)m * ldc + n] = ex1[(size_t)m * CDIM + n] + gte * v + (1.0f - gte) * s;
            }
        }
    }
#undef GEMM_LOAD
#undef GEMM_STS
}

// ---------------- windowed attention, TENSOR-CORE version --------------------
// grid (NWIN, 3), block 128 (4 warps). Per block: one (window, head).
// Scores: S(64x56, valid 49x49) = Q(64x32) @ K^T via m16n8k8 3xTF32.
// AV:     O(64x32) = P(64x56) @ V via m16n8k8 3xTF32, V stored transposed.
// Padding: q rows 49..63 zero, k rows 49..55 zero, vsT cols 49..55 zero,
// ps cols 49..55 zeroed during softmax -> no NaN reaches valid outputs.
__global__ __launch_bounds__(128) void attn3_kernel(
    const float* __restrict__ qkv, float* __restrict__ ao)
{
    __shared__ __align__(16) float qs[64][36];   // pitch 36: frag loads conflict-free
    __shared__ __align__(16) float ks[56][36];
    __shared__ float vsT[32][60];                // V transposed: vsT[d][t]
    __shared__ float ps[64][60];
    __shared__ int ltab[49];
    __shared__ int otab[49];

    int w  = blockIdx.x;
    int h  = blockIdx.y;
    int b  = w >> 6;
    int wh = (w >> 3) & 7;
    int ww = w & 7;
    int tid  = threadIdx.x;
    int warp = tid >> 5;
    int lane = tid & 31;
    int gid  = lane >> 2;     // 0..7
    int tig  = lane & 3;      // 0..3

    if (tid < 49) {
        int th = tid / 7, tw = tid % 7;
        int r = (wh * 7 + th + 3) % IMGHW;
        int c = (ww * 7 + tw + 3) % IMGHW;
        ltab[tid] = b * (IMGHW * IMGHW) + r * IMGHW + c;
        int ro = wh * 7 + (th + 3) % 7;          // intra-window inverse roll
        int co = ww * 7 + (tw + 3) % 7;
        otab[tid] = b * (IMGHW * IMGHW) + ro * IMGHW + co;
    }
    // zero pads
    for (int i = tid; i < 15 * 36; i += 128) qs[49 + i / 36][i % 36] = 0.0f;
    for (int i = tid; i < 7 * 36; i += 128)  ks[49 + i / 36][i % 36] = 0.0f;
    for (int i = tid; i < 32 * 11; i += 128) vsT[i / 11][49 + i % 11] = 0.0f;
    __syncthreads();

    // load q/k rows; v transposed
    for (int i = tid; i < 49 * 8; i += 128) {
        int t = i >> 3, dq = (i & 7) * 4;
        const float* base = qkv + (size_t)ltab[t] * QKVDIM + h * 32 + dq;
        *(float4*)&qs[t][dq] = *(const float4*)base;
        *(float4*)&ks[t][dq] = *(const float4*)(base + 96);
        float4 v = *(const float4*)(base + 192);
        vsT[dq][t]     = v.x;
        vsT[dq + 1][t] = v.y;
        vsT[dq + 2][t] = v.z;
        vsT[dq + 3][t] = v.w;
    }
    __syncthreads();

    const float scale = 0.17677669529663687f;  // 1/sqrt(32)

    // ---- scores: warp = m-tile (16 rows); 7 n-tiles x 4 k-tiles x 3 mma ----
    {
        int mrow = warp * 16 + gid;
        unsigned ah[4][4], al[4][4];
#pragma unroll
        for (int kt = 0; kt < 4; kt++) {
            int kc = kt * 8 + tig;
            float a0 = qs[mrow][kc];
            float a1 = qs[mrow + 8][kc];
            float a2 = qs[mrow][kc + 4];
            float a3 = qs[mrow + 8][kc + 4];
            SPLIT2(ah[kt][0], al[kt][0], a0);
            SPLIT2(ah[kt][1], al[kt][1], a1);
            SPLIT2(ah[kt][2], al[kt][2], a2);
            SPLIT2(ah[kt][3], al[kt][3], a3);
        }
#pragma unroll
        for (int nt = 0; nt < 7; nt++) {
            unsigned bh[4][2], bl[4][2];
#pragma unroll
            for (int kt = 0; kt < 4; kt++) {
                int kc = kt * 8 + tig;
                float b0 = ks[nt * 8 + gid][kc];
                float b1 = ks[nt * 8 + gid][kc + 4];
                SPLIT2(bh[kt][0], bl[kt][0], b0);
                SPLIT2(bh[kt][1], bl[kt][1], b1);
            }
            float acc[4] = {0.0f, 0.0f, 0.0f, 0.0f};
#pragma unroll
            for (int kt = 0; kt < 4; kt++) {
                mma_tf32(acc, ah[kt], bh[kt]);
                mma_tf32(acc, al[kt], bh[kt]);
                mma_tf32(acc, ah[kt], bl[kt]);
            }
            int c = nt * 8 + tig * 2;
            if (c < 49) {
                ps[mrow][c]     = acc[0] * scale;
                ps[mrow + 8][c] = acc[2] * scale;
            }
            if (c + 1 < 49) {
                ps[mrow][c + 1]     = acc[1] * scale;
                ps[mrow + 8][c + 1] = acc[3] * scale;
            }
        }
    }
    __syncthreads();

    // softmax: 2 threads per row (rows 0..48); also zero pad cols 49..55
    if (tid < 98) {
        int row = tid >> 1, half = tid & 1;
        int c0 = half ? 25 : 0;
        int c1 = half ? 49 : 25;
        unsigned mask = (tid < 96) ? 0xffffffffu : 0x3u;
        float mx = -1e30f;
        for (int j = c0; j < c1; j++) mx = fmaxf(mx, ps[row][j]);
        mx = fmaxf(mx, __shfl_xor_sync(mask, mx, 1));
        float sum = 0.0f;
        for (int j = c0; j < c1; j++) {
            float e = expf(ps[row][j] - mx);
            ps[row][j] = e;
            sum += e;
        }
        sum += __shfl_xor_sync(mask, sum, 1);
        float inv = 1.0f / sum;
        for (int j = c0; j < c1; j++) ps[row][j] *= inv;
        if (half) {
#pragma unroll
            for (int j = 49; j < 56; j++) ps[row][j] = 0.0f;
        }
    }
    __syncthreads();

    // ---- AV: O(64x32) = P @ V; warp = m-tile; 4 n-tiles x 7 k-tiles x 3 ----
    {
        int mrow = warp * 16 + gid;
        unsigned ah[7][4], al[7][4];
#pragma unroll
        for (int kt = 0; kt < 7; kt++) {
            int kc = kt * 8 + tig;
            float a0 = ps[mrow][kc];
            float a1 = ps[mrow + 8][kc];
            float a2 = ps[mrow][kc + 4];
            float a3 = ps[mrow + 8][kc + 4];
            SPLIT2(ah[kt][0], al[kt][0], a0);
            SPLIT2(ah[kt][1], al[kt][1], a1);
            SPLIT2(ah[kt][2], al[kt][2], a2);
            SPLIT2(ah[kt][3], al[kt][3], a3);
        }
#pragma unroll
        for (int nt = 0; nt < 4; nt++) {
            unsigned bh[7][2], bl[7][2];
#pragma unroll
            for (int kt = 0; kt < 7; kt++) {
                int kc = kt * 8 + tig;
                float b0 = vsT[nt * 8 + gid][kc];
                float b1 = vsT[nt * 8 + gid][kc + 4];
                SPLIT2(bh[kt][0], bl[kt][0], b0);
                SPLIT2(bh[kt][1], bl[kt][1], b1);
            }
            float acc[4] = {0.0f, 0.0f, 0.0f, 0.0f};
#pragma unroll
            for (int kt = 0; kt < 7; kt++) {
                mma_tf32(acc, ah[kt], bh[kt]);
                mma_tf32(acc, al[kt], bh[kt]);
                mma_tf32(acc, ah[kt], bl[kt]);
            }
            int d = nt * 8 + tig * 2;
            int t0 = mrow, t1 = mrow + 8;
            if (t0 < 49) {
                float2 o = {acc[0], acc[1]};
                *(float2*)&ao[(size_t)otab[t0] * CDIM + h * 32 + d] = o;
            }
            if (t1 < 49) {
                float2 o = {acc[2], acc[3]};
                *(float2*)&ao[(size_t)otab[t1] * CDIM + h * 32 + d] = o;
            }
        }
    }
}

// ---------------- host launcher ----------------------------------------------
extern "C" void kernel_launch(void* const* d_in, const int* in_sizes, int n_in,
                              void* d_out, int out_size)
{
    const float* x       = (const float*)d_in[0];
    const float* n1g     = (const float*)d_in[1];
    const float* n1b     = (const float*)d_in[2];
    const float* qkv_w   = (const float*)d_in[3];
    const float* qkv_b   = (const float*)d_in[4];
    const float* proj_w  = (const float*)d_in[5];
    const float* proj_b  = (const float*)d_in[6];
    const float* n2g     = (const float*)d_in[7];
    const float* n2b     = (const float*)d_in[8];
    const float* fng     = (const float*)d_in[9];
    const float* fnb     = (const float*)d_in[10];
    const float* pin_w   = (const float*)d_in[11];
    const float* pin_b   = (const float*)d_in[12];
    const float* tm_inc  = (const float*)d_in[13];
    const float* tm_out  = (const float*)d_in[14];
    const float* gate    = (const float*)d_in[15];
    float* out           = (float*)d_out;

    float *p_mu, *p_rs, *p_qkv, *p_ao, *p_x1, *p_w, *p_ll, *p_cl;
    int* p_skip;
    cudaGetSymbolAddress((void**)&p_mu,  g_mu);
    cudaGetSymbolAddress((void**)&p_rs,  g_rs);
    cudaGetSymbolAddress((void**)&p_qkv, g_qkv);
    cudaGetSymbolAddress((void**)&p_ao,  g_ao);
    cudaGetSymbolAddress((void**)&p_x1,  g_x1);
    cudaGetSymbolAddress((void**)&p_w,   g_w);
    cudaGetSymbolAddress((void**)&p_ll,  g_ll);
    cudaGetSymbolAddress((void**)&p_cl,  g_cl);
    cudaGetSymbolAddress((void**)&p_skip, g_skip);

    // opt-in dynamic smem for the TC GEMM (>48KB); idempotent, not captured
    static bool attr_done = false;
    if (!attr_done) {
        cudaFuncSetAttribute(gemmtc_k<1, true>,
                             cudaFuncAttributeMaxDynamicSharedMemorySize, TC_SMEM);
        cudaFuncSetAttribute(gemmtc_k<2, false>,
                             cudaFuncAttributeMaxDynamicSharedMemorySize, TC_SMEM);
        attr_done = true;
    }

    const int MB = NTOK / 128;  // 392

    // 0) guard: decide whether the clause branch is provably negligible
    guard_kernel<<<1, 1024>>>(tm_inc, tm_out, p_skip);

    // 1) LN1 stats (mean/rstd only; LN applied inside the qkv GEMM A-load)
    ln1_stats<<<NTOK / 8, 256>>>(x, p_mu, p_rs);

    // 2) QKV GEMM (tensor cores, 3xTF32) with fused LN1
    gemmtc_k<1, true><<<dim3(MB, QKVDIM / 96), 256, TC_SMEM>>>(
        x, qkv_w, qkv_b, nullptr, p_qkv, QKVDIM,
        p_mu, p_rs, n1g, n1b, nullptr, nullptr, p_skip);

    // 3) windowed attention: tensor cores, one block per (window, head)
    attn3_kernel<<<dim3(NWIN, 3), 128>>>(p_qkv, p_ao);

    // 4) proj + residual (tensor cores); fast path writes final output
    gemmtc_k<2, false><<<dim3(MB, 1), 256, TC_SMEM>>>(
        p_ao, proj_w, proj_b, x, p_x1, CDIM,
        nullptr, nullptr, nullptr, nullptr, out, gate, p_skip);

    // 5) double layernorm -> g_w   (skipped on fast path)
    ln2_kernel<<<NTOK / 8, 256>>>(p_x1, n2g, n2b, fng, fnb, p_w, p_skip);

    // 6) pin GEMM + sigmoid + log-literals -> g_ll   (skipped on fast path)
    gemm2_k<3, false, false, 1><<<dim3(MB, (HIDDIM + 127) / 128), 256>>>(
        p_w, pin_w, pin_b, nullptr, nullptr, p_ll,
        NTOK, HIDDIM, CDIM, LITDIM, p_skip);

    // 7) clause GEMM, binary mask, exp epilogue -> g_cl (skipped on fast path)
    gemm2_k<4, false, true, 1><<<dim3(MB, 1), 256>>>(
        p_ll, tm_inc, nullptr, nullptr, nullptr, p_cl,
        NTOK, NCLAUSE, LITDIM, NCLAUSE, p_skip);

    // 8) final GEMM: full path only (fast path already wrote out in step 4)
    gemm2_k<5, true, false, 1><<<dim3(MB, 1), 256>>>(
        p_cl, tm_out, nullptr, p_x1, gate, out,
        NTOK, CDIM, NCLAUSE, CDIM, p_skip);

    (void)in_sizes; (void)n_in; (void)out_size;
}